// round 3
// baseline (speedup 1.0000x reference)
#include <cuda_runtime.h>
#include <math.h>

#define BB   16
#define LL   4096
#define DD   256
#define CC   50
#define NN   512
#define EE   8192
#define FF   100
#define FP   128
#define AA   256
#define FFNH 128
#define FEAT 556   /* 256 + 3*100 */

// ---------------- one big static scratch buffer (no allocations) ------------
static constexpr size_t OFF_H     = 0;
static constexpr size_t OFF_T0    = OFF_H     + (size_t)BB*LL*DD;
static constexpr size_t OFF_T1    = OFF_T0    + (size_t)BB*LL*FF;
static constexpr size_t OFF_Z     = OFF_T1    + (size_t)BB*LL*FF;
static constexpr size_t OFF_LOG   = OFF_Z     + (size_t)BB*AA*LL;
static constexpr size_t OFF_RMAX  = OFF_LOG   + (size_t)BB*CC*LL;
static constexpr size_t OFF_RSINV = OFF_RMAX  + (size_t)BB*CC;
static constexpr size_t OFF_VPART = OFF_RSINV + (size_t)BB*CC;
static constexpr size_t OFF_V     = OFF_VPART + (size_t)16*BB*CC*FF;
static constexpr size_t OFF_WA    = OFF_V     + (size_t)3*BB*CC*FF;
static constexpr size_t OFF_WB    = OFF_WA    + (size_t)9*DD*FP;
static constexpr size_t OFF_XN    = OFF_WB    + (size_t)9*FF*FP;
static constexpr size_t OFF_XW    = OFF_XN    + (size_t)BB*NN*DD;
static constexpr size_t OFF_G1    = OFF_XW    + (size_t)BB*NN*DD;
static constexpr size_t OFF_GOUT  = OFF_G1    + (size_t)BB*NN*DD;
static constexpr size_t OFF_F1T   = OFF_GOUT  + (size_t)BB*CC*DD;
static constexpr size_t OFF_DINV  = OFF_F1T   + (size_t)FEAT*FFNH;
static constexpr size_t BUF_TOTAL = OFF_DINV  + (size_t)BB*NN;

__device__ float g_buf[BUF_TOTAL];
__device__ int   g_deg[BB*NN];

// ---------------- embedding gather  h[b][l][d] ------------------------------
__global__ void k_embed(const int* __restrict__ x, const float* __restrict__ emb,
                        float* __restrict__ h) {
    size_t idx = (size_t)blockIdx.x * 256 + threadIdx.x;
    if (idx >= (size_t)BB*LL*DD) return;
    int d = (int)(idx & (DD - 1));
    size_t row = idx >> 8;
    h[idx] = emb[(size_t)x[row] * DD + d];
}

// -------- weight transpose/pad: w[F][CIN][K] -> wT[K][CIN][FP] (F padded) ---
__global__ void k_prepw(const float* __restrict__ w, float* __restrict__ wT,
                        int K, int CIN) {
    int idx = blockIdx.x * 256 + threadIdx.x;
    int tot = K * CIN * FP;
    if (idx >= tot) return;
    int f = idx % FP;
    int rem = idx / FP;
    int d = rem % CIN;
    int k = rem / CIN;
    wT[idx] = (f < FF) ? w[(f * CIN + d) * K + k] : 0.f;
}

// ---------------- conv1d 'same' + fused tanh/BN/residual --------------------
// in:[B][L][CIN]  wT:[K][CIN][FP]  out:[B][L][FF]
// mode 0: out = tanh(acc + cb[f])*sc + bt
// mode 1: out = tanh(acc*sc + bt + resid[b][l][f])
template<int K, int CIN>
__global__ void k_conv(const float* __restrict__ in, const float* __restrict__ wT,
                       const float* __restrict__ cb, const float* __restrict__ gamma,
                       const float* __restrict__ beta, const float* __restrict__ resid,
                       float* __restrict__ out, int mode) {
    constexpr int LT = 64;
    constexpr int PAD = K / 2;
    constexpr int ROWS = LT + K - 1;
    __shared__ float s_in[ROWS][32];
    __shared__ float s_w[32][FP];
    int b = blockIdx.y, l0 = blockIdx.x * LT, tid = threadIdx.x;
    int tf = tid & 31, tl = tid >> 5;
    float acc[8][4];
#pragma unroll
    for (int r = 0; r < 8; r++)
#pragma unroll
        for (int j = 0; j < 4; j++) acc[r][j] = 0.f;
    const float* inb = in + (size_t)b * LL * CIN;

    for (int d0 = 0; d0 < CIN; d0 += 32) {
        int dc = min(32, CIN - d0);
        __syncthreads();
        for (int t = tid; t < ROWS * 32; t += 256) {
            int row = t >> 5, dd = t & 31;
            int gl = l0 - PAD + row;
            float v = 0.f;
            if (dd < dc && gl >= 0 && gl < LL) v = inb[(size_t)gl * CIN + d0 + dd];
            s_in[row][dd] = v;
        }
#pragma unroll
        for (int k = 0; k < K; k++) {
            __syncthreads();
            const float* wk = wT + ((size_t)k * CIN + d0) * FP;
            for (int t = tid; t < 32 * FP; t += 256) {
                int dd = t >> 7, f = t & 127;
                s_w[dd][f] = (dd < dc) ? wk[dd * FP + f] : 0.f;
            }
            __syncthreads();
#pragma unroll 4
            for (int dd = 0; dd < dc; dd++) {
                float w0 = s_w[dd][tf], w1 = s_w[dd][tf + 32],
                      w2 = s_w[dd][tf + 64], w3 = s_w[dd][tf + 96];
#pragma unroll
                for (int r = 0; r < 8; r++) {
                    float iv = s_in[tl * 8 + r + k][dd];
                    acc[r][0] += iv * w0; acc[r][1] += iv * w1;
                    acc[r][2] += iv * w2; acc[r][3] += iv * w3;
                }
            }
        }
    }
    const float BNI = rsqrtf(1.f + 1e-5f);
#pragma unroll
    for (int r = 0; r < 8; r++) {
        int l = l0 + tl * 8 + r;
        size_t base = ((size_t)b * LL + l) * FF;
#pragma unroll
        for (int j = 0; j < 4; j++) {
            int f = tf + 32 * j;
            if (f < FF) {
                float v = acc[r][j];
                float sc = gamma[f] * BNI, bt = beta[f];
                if (mode == 0) v = tanhf(v + cb[f]) * sc + bt;
                else           v = tanhf(v * sc + bt + resid[base + f]);
                out[base + f] = v;
            }
        }
    }
}

// ---------------- Z[b][a][l] = tanh(sum_f aw[a][f]*t[b][l][f]) --------------
__global__ void k_z(const float* __restrict__ t, const float* __restrict__ aw,
                    float* __restrict__ Z) {
    __shared__ float s_aw[32][101];
    __shared__ float s_t[64][101];
    int a0 = blockIdx.x * 32, l0 = blockIdx.y * 64, b = blockIdx.z;
    int tid = threadIdx.x;                 // 128 threads
    int at = tid >> 4, lt = tid & 15;      // 8 x 16 -> 32 a x 64 l
    for (int idx = tid; idx < 32 * FF; idx += 128) {
        int row = idx / FF, f = idx % FF;
        s_aw[row][f] = aw[(a0 + row) * FF + f];
    }
    for (int idx = tid; idx < 64 * FF; idx += 128) {
        int row = idx / FF, f = idx % FF;
        s_t[row][f] = t[((size_t)b * LL + l0 + row) * FF + f];
    }
    __syncthreads();
    float acc[4][4];
#pragma unroll
    for (int i = 0; i < 4; i++)
#pragma unroll
        for (int j = 0; j < 4; j++) acc[i][j] = 0.f;
    for (int f = 0; f < FF; f++) {
        float av[4], tv[4];
#pragma unroll
        for (int i = 0; i < 4; i++) av[i] = s_aw[at * 4 + i][f];
#pragma unroll
        for (int j = 0; j < 4; j++) tv[j] = s_t[lt * 4 + j][f];
#pragma unroll
        for (int i = 0; i < 4; i++)
#pragma unroll
            for (int j = 0; j < 4; j++) acc[i][j] += av[i] * tv[j];
    }
#pragma unroll
    for (int i = 0; i < 4; i++) {
        float4 v;
        v.x = tanhf(acc[i][0]); v.y = tanhf(acc[i][1]);
        v.z = tanhf(acc[i][2]); v.w = tanhf(acc[i][3]);
        size_t o = ((size_t)b * AA + a0 + at * 4 + i) * LL + l0 + lt * 4;
        *reinterpret_cast<float4*>(Z + o) = v;
    }
}

// ---------------- logits[b][c][l] = sum_a au[c][a]*Z[b][a][l] ---------------
__global__ void k_logits(const float* __restrict__ Z, const float* __restrict__ au,
                         float* __restrict__ logits) {
    __shared__ float s_au[CC * 128];
    int l = blockIdx.x * 256 + threadIdx.x;
    int b = blockIdx.y;
    float acc[CC];
#pragma unroll
    for (int c = 0; c < CC; c++) acc[c] = 0.f;
    for (int ch = 0; ch < 2; ch++) {
        __syncthreads();
        for (int idx = threadIdx.x; idx < CC * 128; idx += 256) {
            int c = idx >> 7, a = idx & 127;
            s_au[idx] = au[c * AA + ch * 128 + a];
        }
        __syncthreads();
        for (int a = 0; a < 128; a++) {
            float z = Z[((size_t)b * AA + ch * 128 + a) * LL + l];
#pragma unroll
            for (int c = 0; c < CC; c++) acc[c] += s_au[(c << 7) + a] * z;
        }
    }
#pragma unroll
    for (int c = 0; c < CC; c++)
        logits[((size_t)b * CC + c) * LL + l] = acc[c];
}

// ---------------- softmax stats per (b,c) row of length L -------------------
__global__ void k_soft(const float* __restrict__ logits, float* __restrict__ rmax,
                       float* __restrict__ rsinv) {
    __shared__ float sred[256];
    int c = blockIdx.x, b = blockIdx.y, tid = threadIdx.x;
    const float* row = logits + ((size_t)b * CC + c) * LL;
    float m = -1e30f;
    for (int l = tid; l < LL; l += 256) m = fmaxf(m, row[l]);
    sred[tid] = m; __syncthreads();
    for (int s = 128; s > 0; s >>= 1) {
        if (tid < s) sred[tid] = fmaxf(sred[tid], sred[tid + s]);
        __syncthreads();
    }
    m = sred[0]; __syncthreads();
    float sum = 0.f;
    for (int l = tid; l < LL; l += 256) sum += expf(row[l] - m);
    sred[tid] = sum; __syncthreads();
    for (int s = 128; s > 0; s >>= 1) {
        if (tid < s) sred[tid] += sred[tid + s];
        __syncthreads();
    }
    if (tid == 0) { rmax[b * CC + c] = m; rsinv[b * CC + c] = 1.f / sred[0]; }
}

// ---------------- V partials: vpart[chunk][b][c][f] -------------------------
__global__ void k_v(const float* __restrict__ t, const float* __restrict__ logits,
                    const float* __restrict__ rmax, const float* __restrict__ rsinv,
                    float* __restrict__ vpart) {
    __shared__ float s_w[25][256];
    int cgrp = blockIdx.x, chunk = blockIdx.y, b = blockIdx.z;
    int tid = threadIdx.x;                 // 128 threads
    int l0 = chunk * 256;
    for (int idx = tid; idx < 25 * 256; idx += 128) {
        int cl = idx >> 8, ll = idx & 255;
        int c = cgrp * 25 + cl;
        float m = rmax[b * CC + c], si = rsinv[b * CC + c];
        s_w[cl][ll] = expf(logits[((size_t)b * CC + c) * LL + l0 + ll] - m) * si;
    }
    __syncthreads();
    float acc[25];
#pragma unroll
    for (int c = 0; c < 25; c++) acc[c] = 0.f;
    int f = tid;
    for (int ll = 0; ll < 256; ll++) {
        float tv = (f < FF) ? t[((size_t)b * LL + l0 + ll) * FF + f] : 0.f;
#pragma unroll
        for (int c = 0; c < 25; c++) acc[c] += s_w[c][ll] * tv;
    }
    if (f < FF) {
#pragma unroll
        for (int c = 0; c < 25; c++) {
            int cg = cgrp * 25 + c;
            vpart[(((size_t)chunk * BB + b) * CC + cg) * FF + f] = acc[c];
        }
    }
}

__global__ void k_vred(const float* __restrict__ vpart, float* __restrict__ V) {
    int idx = blockIdx.x * 256 + threadIdx.x;
    if (idx >= BB * CC * FF) return;
    float s = 0.f;
#pragma unroll
    for (int ch = 0; ch < 16; ch++) s += vpart[(size_t)ch * BB * CC * FF + idx];
    V[idx] = s;
}

// ---------------- GCN ------------------------------------------------------
__global__ void k_nodes(const int* __restrict__ nodes, const float* __restrict__ emb,
                        float* __restrict__ xn) {
    size_t idx = (size_t)blockIdx.x * 256 + threadIdx.x;
    if (idx >= (size_t)BB * NN * DD) return;
    int d = (int)(idx & (DD - 1));
    size_t row = idx >> 8;
    xn[idx] = emb[(size_t)nodes[row] * DD + d];
}

__global__ void k_deginit(int* __restrict__ deg) {
    int idx = blockIdx.x * 256 + threadIdx.x;
    if (idx < BB * NN) deg[idx] = 1;   // self loop
}

__global__ void k_degadd(const int* __restrict__ edges, int* __restrict__ deg) {
    int idx = blockIdx.x * 256 + threadIdx.x;
    if (idx >= BB * EE) return;
    int b = idx / EE, e = idx % EE;
    int dst = edges[(b * 2 + 1) * EE + e];
    atomicAdd(&deg[b * NN + dst], 1);
}

__global__ void k_dinv(const int* __restrict__ deg, float* __restrict__ dinv) {
    int idx = blockIdx.x * 256 + threadIdx.x;
    if (idx < BB * NN) dinv[idx] = rsqrtf((float)deg[idx]);
}

// out[b][n][o] = sum_i A[b][n][i] * W[o][i]   (64x64 tile, 256 thr, 4x4/thr)
__global__ void k_gemm(const float* __restrict__ A, const float* __restrict__ W,
                       float* __restrict__ out) {
    __shared__ float s_a[64][33];
    __shared__ float s_b[64][33];
    int o0 = blockIdx.x * 64, n0 = blockIdx.y * 64, b = blockIdx.z;
    int tid = threadIdx.x;                 // 256 threads
    int ot = tid >> 4, nt = tid & 15;      // 16 x 16 -> 64 x 64
    float acc[4][4];
#pragma unroll
    for (int u = 0; u < 4; u++)
#pragma unroll
        for (int v = 0; v < 4; v++) acc[u][v] = 0.f;
    for (int i0 = 0; i0 < DD; i0 += 32) {
        __syncthreads();
        for (int idx = tid; idx < 64 * 32; idx += 256) {
            int row = idx >> 5, ii = idx & 31;
            s_a[row][ii] = A[((size_t)b * NN + n0 + row) * DD + i0 + ii];
            s_b[row][ii] = W[(size_t)(o0 + row) * DD + i0 + ii];
        }
        __syncthreads();
#pragma unroll 4
        for (int ii = 0; ii < 32; ii++) {
            float wv[4], av[4];
#pragma unroll
            for (int u = 0; u < 4; u++) wv[u] = s_b[ot * 4 + u][ii];
#pragma unroll
            for (int v = 0; v < 4; v++) av[v] = s_a[nt * 4 + v][ii];
#pragma unroll
            for (int u = 0; u < 4; u++)
#pragma unroll
                for (int v = 0; v < 4; v++) acc[u][v] += wv[u] * av[v];
        }
    }
#pragma unroll
    for (int v = 0; v < 4; v++)
#pragma unroll
        for (int u = 0; u < 4; u++)
            out[((size_t)b * NN + n0 + nt * 4 + v) * DD + o0 + ot * 4 + u] = acc[u][v];
}

__global__ void k_self(const float* __restrict__ xw, const float* __restrict__ dinv,
                       float* __restrict__ out, int rows) {
    size_t idx = (size_t)blockIdx.x * 256 + threadIdx.x;
    if (idx >= (size_t)BB * rows * DD) return;
    int o = (int)(idx & (DD - 1));
    size_t row = idx >> 8;
    int b = (int)(row / rows);
    int n = (int)(row % rows);
    float di = dinv[b * NN + n];
    out[idx] = di * di * xw[((size_t)b * NN + n) * DD + o];
}

__global__ void k_edge(const int* __restrict__ edges, const float* __restrict__ dinv,
                       const float* __restrict__ xw, float* __restrict__ out,
                       int dstmax) {
    int b = blockIdx.y;
    int eloc = threadIdx.x >> 5, lane = threadIdx.x & 31;
    int e = blockIdx.x * 8 + eloc;
    int src = edges[(b * 2) * EE + e];
    int dst = edges[(b * 2 + 1) * EE + e];
    if (dst >= dstmax) return;
    float norm = dinv[b * NN + src] * dinv[b * NN + dst];
    const float* xr = xw + ((size_t)b * NN + src) * DD;
    float* orow = out + ((size_t)b * dstmax + dst) * DD;
#pragma unroll
    for (int j = 0; j < 8; j++) {
        int o = lane + j * 32;
        atomicAdd(&orow[o], norm * xr[o]);
    }
}

__global__ void k_post(float* __restrict__ buf, const float* __restrict__ bias,
                       int rows, int dorelu) {
    size_t idx = (size_t)blockIdx.x * 256 + threadIdx.x;
    if (idx >= (size_t)BB * rows * DD) return;
    int o = (int)(idx & (DD - 1));
    float v = buf[idx] + bias[o];
    if (dorelu) v = fmaxf(v, 0.f);
    buf[idx] = v;
}

// ---------------- final MLP --------------------------------------------------
__global__ void k_prepf1(const float* __restrict__ w, float* __restrict__ wT) {
    int idx = blockIdx.x * 256 + threadIdx.x;
    if (idx >= FEAT * FFNH) return;
    int h = idx & (FFNH - 1), k = idx >> 7;
    wT[idx] = w[h * FEAT + k];
}

__global__ void k_final(const float* __restrict__ gout, const float* __restrict__ V,
                        const float* __restrict__ f1T, const float* __restrict__ f1b,
                        const float* __restrict__ f2w, const float* __restrict__ f2b,
                        float* __restrict__ y) {
    __shared__ float s_feat[FEAT];
    __shared__ float s_red[FFNH];
    int c = blockIdx.x, b = blockIdx.y, h = threadIdx.x;   // 128 threads
    for (int idx = h; idx < FEAT; idx += FFNH) {
        float v;
        if (idx < DD) {
            v = gout[((size_t)b * CC + c) * DD + idx];
        } else {
            int br = (idx - DD) / FF;
            int f  = (idx - DD) % FF;
            v = V[(((size_t)br * BB + b) * CC + c) * FF + f];
        }
        s_feat[idx] = v;
    }
    __syncthreads();
    float acc = f1b[h];
    for (int k = 0; k < FEAT; k++) acc += f1T[k * FFNH + h] * s_feat[k];
    float hid = fmaxf(acc, 0.f);
    s_red[h] = f2w[c * FFNH + h] * hid;
    __syncthreads();
    for (int s = 64; s > 0; s >>= 1) {
        if (h < s) s_red[h] += s_red[h + s];
        __syncthreads();
    }
    if (h == 0) y[b * CC + c] = s_red[0] + f2b[c];
}

// ---------------- branch driver ---------------------------------------------
template<int K>
static void run_branch(const float* cw, const float* cb, const float* rw,
                       const float* bn_g, const float* bn_b,
                       const float* aw, const float* au,
                       float* buf, int br) {
    float* h    = buf + OFF_H;
    float* t0   = buf + OFF_T0;
    float* t1   = buf + OFF_T1;
    float* Z    = buf + OFF_Z;
    float* lg   = buf + OFF_LOG;
    float* rmax = buf + OFF_RMAX;
    float* rsin = buf + OFF_RSINV;
    float* vp   = buf + OFF_VPART;
    float* V    = buf + OFF_V + (size_t)br * BB * CC * FF;
    float* wA   = buf + OFF_WA;
    float* wB   = buf + OFF_WB;

    dim3 cgrid(LL / 64, BB);
    k_prepw<<<(K * DD * FP + 255) / 256, 256>>>(cw, wA, K, DD);
    k_conv<K, DD><<<cgrid, 256>>>(h, wA, cb, bn_g, bn_b, nullptr, t0, 0);
    k_prepw<<<(K * FF * FP + 255) / 256, 256>>>(rw, wB, K, FF);
    k_conv<K, FF><<<cgrid, 256>>>(t0, wB, nullptr, bn_g + FF, bn_b + FF, t0, t1, 1);
    k_prepw<<<(K * FF * FP + 255) / 256, 256>>>(rw + (size_t)FF * FF * K, wB, K, FF);
    k_conv<K, FF><<<cgrid, 256>>>(t1, wB, nullptr, bn_g + 2 * FF, bn_b + 2 * FF, t1, t0, 1);

    k_z<<<dim3(AA / 32, LL / 64, BB), 128>>>(t0, aw, Z);
    k_logits<<<dim3(LL / 256, BB), 256>>>(Z, au, lg);
    k_soft<<<dim3(CC, BB), 256>>>(lg, rmax, rsin);
    k_v<<<dim3(2, 16, BB), 128>>>(t0, lg, rmax, rsin, vp);
    k_vred<<<(BB * CC * FF + 255) / 256, 256>>>(vp, V);
}

extern "C" void kernel_launch(void* const* d_in, const int* in_sizes, int n_in,
                              void* d_out, int out_size) {
    const int*   x        = (const int*)d_in[0];
    const int*   nodes    = (const int*)d_in[2];
    const int*   edges    = (const int*)d_in[3];
    const float* word_emb = (const float*)d_in[4];
    const float* ent_emb  = (const float*)d_in[5];
    const float* convw3   = (const float*)d_in[6];
    const float* convb3   = (const float*)d_in[7];
    const float* resw3    = (const float*)d_in[8];
    const float* convw5   = (const float*)d_in[9];
    const float* convb5   = (const float*)d_in[10];
    const float* resw5    = (const float*)d_in[11];
    const float* convw9   = (const float*)d_in[12];
    const float* convb9   = (const float*)d_in[13];
    const float* resw9    = (const float*)d_in[14];
    const float* bn_gamma = (const float*)d_in[15];
    const float* bn_beta  = (const float*)d_in[16];
    const float* attn_w   = (const float*)d_in[17];
    const float* attn_u   = (const float*)d_in[18];
    const float* gc1_w    = (const float*)d_in[19];
    const float* gc1_b    = (const float*)d_in[20];
    const float* gc2_w    = (const float*)d_in[21];
    const float* gc2_b    = (const float*)d_in[22];
    const float* fin1_w   = (const float*)d_in[23];
    const float* fin1_b   = (const float*)d_in[24];
    const float* fin2_w   = (const float*)d_in[25];
    const float* fin2_b   = (const float*)d_in[26];
    float* out = (float*)d_out;

    float* buf; int* deg;
    cudaGetSymbolAddress((void**)&buf, g_buf);
    cudaGetSymbolAddress((void**)&deg, g_deg);

    // embedding
    k_embed<<<(int)(((size_t)BB * LL * DD + 255) / 256), 256>>>(x, word_emb, buf + OFF_H);

    // three encoder branches
    run_branch<3>(convw3, convb3, resw3, bn_gamma + 0 * 3 * FF, bn_beta + 0 * 3 * FF,
                  attn_w + 0 * AA * FF, attn_u + 0 * CC * AA, buf, 0);
    run_branch<5>(convw5, convb5, resw5, bn_gamma + 1 * 3 * FF, bn_beta + 1 * 3 * FF,
                  attn_w + 1 * AA * FF, attn_u + 1 * CC * AA, buf, 1);
    run_branch<9>(convw9, convb9, resw9, bn_gamma + 2 * 3 * FF, bn_beta + 2 * 3 * FF,
                  attn_w + 2 * AA * FF, attn_u + 2 * CC * AA, buf, 2);

    // GCN
    float* xn   = buf + OFF_XN;
    float* xw   = buf + OFF_XW;
    float* g1   = buf + OFF_G1;
    float* gout = buf + OFF_GOUT;
    float* dinv = buf + OFF_DINV;
    k_nodes<<<(int)(((size_t)BB * NN * DD + 255) / 256), 256>>>(nodes, ent_emb, xn);
    k_deginit<<<(BB * NN + 255) / 256, 256>>>(deg);
    k_degadd<<<(BB * EE + 255) / 256, 256>>>(edges, deg);
    k_dinv<<<(BB * NN + 255) / 256, 256>>>(deg, dinv);

    k_gemm<<<dim3(DD / 64, NN / 64, BB), 256>>>(xn, gc1_w, xw);
    k_self<<<(int)(((size_t)BB * NN * DD + 255) / 256), 256>>>(xw, dinv, g1, NN);
    k_edge<<<dim3(EE / 8, BB), 256>>>(edges, dinv, xw, g1, NN);
    k_post<<<(int)(((size_t)BB * NN * DD + 255) / 256), 256>>>(g1, gc1_b, NN, 1);

    k_gemm<<<dim3(DD / 64, NN / 64, BB), 256>>>(g1, gc2_w, xw);
    k_self<<<(int)(((size_t)BB * CC * DD + 255) / 256), 256>>>(xw, dinv, gout, CC);
    k_edge<<<dim3(EE / 8, BB), 256>>>(edges, dinv, xw, gout, CC);
    k_post<<<(int)(((size_t)BB * CC * DD + 255) / 256), 256>>>(gout, gc2_b, CC, 0);

    // final MLP
    k_prepf1<<<(FEAT * FFNH + 255) / 256, 256>>>(fin1_w, buf + OFF_F1T);
    k_final<<<dim3(CC, BB), FFNH>>>(gout, buf + OFF_V, buf + OFF_F1T,
                                    fin1_b, fin2_w, fin2_b, out);
}

// round 4
// speedup vs baseline: 1.6691x; 1.6691x over previous
#include <cuda_runtime.h>
#include <math.h>
#include <stdint.h>

#define BB   16
#define LL   4096
#define DD   256
#define CC   50
#define NN   512
#define EE   8192
#define FF   100
#define FP   128
#define AA   256
#define FFNH 128
#define FEAT 556   /* 256 + 3*100 */

// ---------------- one big static scratch buffer (no allocations) ------------
static constexpr size_t OFF_H     = 0;
static constexpr size_t OFF_T0    = OFF_H     + (size_t)BB*LL*DD;
static constexpr size_t OFF_T1    = OFF_T0    + (size_t)BB*LL*FP;
static constexpr size_t OFF_Z     = OFF_T1    + (size_t)BB*LL*FP;
static constexpr size_t OFF_LOG   = OFF_Z     + (size_t)BB*AA*LL;
static constexpr size_t OFF_RMAX  = OFF_LOG   + (size_t)BB*CC*LL;
static constexpr size_t OFF_RSINV = OFF_RMAX  + (size_t)BB*CC;
static constexpr size_t OFF_VPART = OFF_RSINV + (size_t)BB*CC;
static constexpr size_t OFF_V     = OFF_VPART + (size_t)16*BB*CC*FF;
static constexpr size_t OFF_WA    = OFF_V     + (size_t)3*BB*CC*FF;
static constexpr size_t OFF_WB    = OFF_WA    + (size_t)9*DD*FP;
static constexpr size_t OFF_XN    = OFF_WB    + (size_t)9*FP*FP;
static constexpr size_t OFF_XW    = OFF_XN    + (size_t)BB*NN*DD;
static constexpr size_t OFF_G1    = OFF_XW    + (size_t)BB*NN*DD;
static constexpr size_t OFF_GOUT  = OFF_G1    + (size_t)BB*NN*DD;
static constexpr size_t OFF_F1T   = OFF_GOUT  + (size_t)BB*CC*DD;
static constexpr size_t OFF_DINV  = OFF_F1T   + (size_t)FEAT*FFNH;
static constexpr size_t BUF_TOTAL = OFF_DINV  + (size_t)BB*NN;

__device__ float g_buf[BUF_TOTAL];
__device__ int   g_deg[BB*NN];

// ---------------- helpers ----------------------------------------------------
__device__ __forceinline__ float to_tf32(float x) {
    float r;
    asm("cvt.rna.tf32.f32 %0, %1;" : "=f"(r) : "f"(x));
    return r;
}

__device__ __forceinline__ void mma8(float d[4], const uint32_t a[4],
                                     uint32_t b0, uint32_t b1) {
    asm volatile(
        "mma.sync.aligned.m16n8k8.row.col.f32.tf32.tf32.f32 "
        "{%0,%1,%2,%3}, {%4,%5,%6,%7}, {%8,%9}, {%0,%1,%2,%3};\n"
        : "+f"(d[0]), "+f"(d[1]), "+f"(d[2]), "+f"(d[3])
        : "r"(a[0]), "r"(a[1]), "r"(a[2]), "r"(a[3]), "r"(b0), "r"(b1));
}

// ---------------- embedding gather  h[b][l][d] ------------------------------
__global__ void k_embed(const int* __restrict__ x, const float* __restrict__ emb,
                        float* __restrict__ h) {
    size_t idx = (size_t)blockIdx.x * 256 + threadIdx.x;
    if (idx >= (size_t)BB*LL*DD) return;
    int d = (int)(idx & (DD - 1));
    size_t row = idx >> 8;
    h[idx] = emb[(size_t)x[row] * DD + d];
}

// ---- weight transpose/pad: w[F][CIN][K] -> wT[K][CINP][FP] -----------------
__global__ void k_prepw(const float* __restrict__ w, float* __restrict__ wT,
                        int K, int CIN, int CINP) {
    int idx = blockIdx.x * 256 + threadIdx.x;
    int tot = K * CINP * FP;
    if (idx >= tot) return;
    int f = idx & 127;
    int rem = idx >> 7;
    int d = rem % CINP;
    int k = rem / CINP;
    wT[idx] = (f < FF && d < CIN) ? w[(f * CIN + d) * K + k] : 0.f;
}

// ---------------- conv1d 'same' via tf32 mma, fused tanh/BN/residual --------
// in:[B][L][CINP]  wT:[K][CINP][FP]  out:[B][L][FP] (f>=FF set to 0)
// mode 0: out = tanh(acc + cb[f])*sc + bt
// mode 1: out = tanh(acc*sc + bt + resid[b][l][f])
template<int K, int CINP>
__global__ void __launch_bounds__(256, 2)
k_conv_mma(const float* __restrict__ in, const float* __restrict__ wT,
           const float* __restrict__ cb, const float* __restrict__ gamma,
           const float* __restrict__ beta, const float* __restrict__ resid,
           float* __restrict__ out, int mode) {
    constexpr int LT = 128;
    constexpr int PAD = K / 2;
    constexpr int ROWS = LT + K - 1;
    constexpr int ISTR = 36;    // bank = (4*row + col) & 31 -> conflict-free A frags
    constexpr int WSTR = 136;   // bank = (8*row + col) & 31 -> conflict-free B frags
    __shared__ float s_in[ROWS * ISTR];
    __shared__ float s_w[32 * WSTR];

    int b = blockIdx.y, l0 = blockIdx.x * LT, tid = threadIdx.x;
    int wid = tid >> 5, lane = tid & 31;
    int wl = wid >> 1, wf = wid & 1;      // 4 L-warps x 2 F-warps
    int grp = lane >> 2, thr = lane & 3;

    float acc[2][8][4];
#pragma unroll
    for (int mi = 0; mi < 2; mi++)
#pragma unroll
        for (int ni = 0; ni < 8; ni++)
#pragma unroll
            for (int ci = 0; ci < 4; ci++) acc[mi][ni][ci] = 0.f;

    const float* inb = in + (size_t)b * LL * CINP;

    for (int d0 = 0; d0 < CINP; d0 += 32) {
        __syncthreads();
        for (int t = tid; t < ROWS * 32; t += 256) {
            int row = t >> 5, dd = t & 31;
            int gl = l0 - PAD + row;
            float v = (gl >= 0 && gl < LL) ? inb[(size_t)gl * CINP + d0 + dd] : 0.f;
            s_in[row * ISTR + dd] = to_tf32(v);
        }
#pragma unroll
        for (int k = 0; k < K; k++) {
            __syncthreads();
            const float* wk = wT + ((size_t)k * CINP + d0) * FP;
            for (int t = tid; t < 32 * FP; t += 256) {
                int dd = t >> 7, f = t & 127;
                s_w[dd * WSTR + f] = to_tf32(wk[dd * FP + f]);
            }
            __syncthreads();
#pragma unroll
            for (int ds = 0; ds < 32; ds += 8) {
                uint32_t a[2][4];
#pragma unroll
                for (int mi = 0; mi < 2; mi++) {
                    int r0 = wl * 32 + mi * 16 + grp + k;
                    a[mi][0] = __float_as_uint(s_in[r0 * ISTR + ds + thr]);
                    a[mi][1] = __float_as_uint(s_in[(r0 + 8) * ISTR + ds + thr]);
                    a[mi][2] = __float_as_uint(s_in[r0 * ISTR + ds + thr + 4]);
                    a[mi][3] = __float_as_uint(s_in[(r0 + 8) * ISTR + ds + thr + 4]);
                }
#pragma unroll
                for (int ni = 0; ni < 8; ni++) {
                    int f = wf * 64 + ni * 8 + grp;
                    uint32_t b0 = __float_as_uint(s_w[(ds + thr) * WSTR + f]);
                    uint32_t b1 = __float_as_uint(s_w[(ds + thr + 4) * WSTR + f]);
                    mma8(acc[0][ni], a[0], b0, b1);
                    mma8(acc[1][ni], a[1], b0, b1);
                }
            }
        }
    }

    const float BNI = rsqrtf(1.f + 1e-5f);
#pragma unroll
    for (int mi = 0; mi < 2; mi++) {
#pragma unroll
        for (int ci = 0; ci < 4; ci++) {
            int l = l0 + wl * 32 + mi * 16 + grp + ((ci >= 2) ? 8 : 0);
            size_t base = ((size_t)b * LL + l) * FP;
#pragma unroll
            for (int ni = 0; ni < 8; ni++) {
                int f = wf * 64 + ni * 8 + 2 * thr + (ci & 1);
                float v = acc[mi][ni][ci];
                float o;
                if (f < FF) {
                    float sc = gamma[f] * BNI, bt = beta[f];
                    if (mode == 0) o = tanhf(v + cb[f]) * sc + bt;
                    else           o = tanhf(v * sc + bt + resid[base + f]);
                } else {
                    o = 0.f;
                }
                out[base + f] = o;
            }
        }
    }
}

// ---------------- Z[b][a][l] = tanh(sum_f aw[a][f]*t[b][l][f]) --------------
__global__ void k_z(const float* __restrict__ t, const float* __restrict__ aw,
                    float* __restrict__ Z) {
    __shared__ float s_aw[32][101];
    __shared__ float s_t[64][101];
    int a0 = blockIdx.x * 32, l0 = blockIdx.y * 64, b = blockIdx.z;
    int tid = threadIdx.x;                 // 128 threads
    int at = tid >> 4, lt = tid & 15;      // 8 x 16 -> 32 a x 64 l
    for (int idx = tid; idx < 32 * FF; idx += 128) {
        int row = idx / FF, f = idx % FF;
        s_aw[row][f] = aw[(a0 + row) * FF + f];
    }
    for (int idx = tid; idx < 64 * FF; idx += 128) {
        int row = idx / FF, f = idx % FF;
        s_t[row][f] = t[((size_t)b * LL + l0 + row) * FP + f];
    }
    __syncthreads();
    float acc[4][4];
#pragma unroll
    for (int i = 0; i < 4; i++)
#pragma unroll
        for (int j = 0; j < 4; j++) acc[i][j] = 0.f;
    for (int f = 0; f < FF; f++) {
        float av[4], tv[4];
#pragma unroll
        for (int i = 0; i < 4; i++) av[i] = s_aw[at * 4 + i][f];
#pragma unroll
        for (int j = 0; j < 4; j++) tv[j] = s_t[lt * 4 + j][f];
#pragma unroll
        for (int i = 0; i < 4; i++)
#pragma unroll
            for (int j = 0; j < 4; j++) acc[i][j] += av[i] * tv[j];
    }
#pragma unroll
    for (int i = 0; i < 4; i++) {
        float4 v;
        v.x = tanhf(acc[i][0]); v.y = tanhf(acc[i][1]);
        v.z = tanhf(acc[i][2]); v.w = tanhf(acc[i][3]);
        size_t o = ((size_t)b * AA + a0 + at * 4 + i) * LL + l0 + lt * 4;
        *reinterpret_cast<float4*>(Z + o) = v;
    }
}

// ---------------- logits[b][c][l] = sum_a au[c][a]*Z[b][a][l] ---------------
__global__ void k_logits(const float* __restrict__ Z, const float* __restrict__ au,
                         float* __restrict__ logits) {
    __shared__ float s_au[CC * 128];
    int l = blockIdx.x * 256 + threadIdx.x;
    int b = blockIdx.y;
    float acc[CC];
#pragma unroll
    for (int c = 0; c < CC; c++) acc[c] = 0.f;
    for (int ch = 0; ch < 2; ch++) {
        __syncthreads();
        for (int idx = threadIdx.x; idx < CC * 128; idx += 256) {
            int c = idx >> 7, a = idx & 127;
            s_au[idx] = au[c * AA + ch * 128 + a];
        }
        __syncthreads();
        for (int a = 0; a < 128; a++) {
            float z = Z[((size_t)b * AA + ch * 128 + a) * LL + l];
#pragma unroll
            for (int c = 0; c < CC; c++) acc[c] += s_au[(c << 7) + a] * z;
        }
    }
#pragma unroll
    for (int c = 0; c < CC; c++)
        logits[((size_t)b * CC + c) * LL + l] = acc[c];
}

// ---------------- softmax stats per (b,c) row of length L -------------------
__global__ void k_soft(const float* __restrict__ logits, float* __restrict__ rmax,
                       float* __restrict__ rsinv) {
    __shared__ float sred[256];
    int c = blockIdx.x, b = blockIdx.y, tid = threadIdx.x;
    const float* row = logits + ((size_t)b * CC + c) * LL;
    float m = -1e30f;
    for (int l = tid; l < LL; l += 256) m = fmaxf(m, row[l]);
    sred[tid] = m; __syncthreads();
    for (int s = 128; s > 0; s >>= 1) {
        if (tid < s) sred[tid] = fmaxf(sred[tid], sred[tid + s]);
        __syncthreads();
    }
    m = sred[0]; __syncthreads();
    float sum = 0.f;
    for (int l = tid; l < LL; l += 256) sum += expf(row[l] - m);
    sred[tid] = sum; __syncthreads();
    for (int s = 128; s > 0; s >>= 1) {
        if (tid < s) sred[tid] += sred[tid + s];
        __syncthreads();
    }
    if (tid == 0) { rmax[b * CC + c] = m; rsinv[b * CC + c] = 1.f / sred[0]; }
}

// ---------------- V partials: vpart[chunk][b][c][f] -------------------------
__global__ void k_v(const float* __restrict__ t, const float* __restrict__ logits,
                    const float* __restrict__ rmax, const float* __restrict__ rsinv,
                    float* __restrict__ vpart) {
    __shared__ float s_w[25][256];
    int cgrp = blockIdx.x, chunk = blockIdx.y, b = blockIdx.z;
    int tid = threadIdx.x;                 // 128 threads
    int l0 = chunk * 256;
    for (int idx = tid; idx < 25 * 256; idx += 128) {
        int cl = idx >> 8, ll = idx & 255;
        int c = cgrp * 25 + cl;
        float m = rmax[b * CC + c], si = rsinv[b * CC + c];
        s_w[cl][ll] = expf(logits[((size_t)b * CC + c) * LL + l0 + ll] - m) * si;
    }
    __syncthreads();
    float acc[25];
#pragma unroll
    for (int c = 0; c < 25; c++) acc[c] = 0.f;
    int f = tid;
    for (int ll = 0; ll < 256; ll++) {
        float tv = (f < FF) ? t[((size_t)b * LL + l0 + ll) * FP + f] : 0.f;
#pragma unroll
        for (int c = 0; c < 25; c++) acc[c] += s_w[c][ll] * tv;
    }
    if (f < FF) {
#pragma unroll
        for (int c = 0; c < 25; c++) {
            int cg = cgrp * 25 + c;
            vpart[(((size_t)chunk * BB + b) * CC + cg) * FF + f] = acc[c];
        }
    }
}

__global__ void k_vred(const float* __restrict__ vpart, float* __restrict__ V) {
    int idx = blockIdx.x * 256 + threadIdx.x;
    if (idx >= BB * CC * FF) return;
    float s = 0.f;
#pragma unroll
    for (int ch = 0; ch < 16; ch++) s += vpart[(size_t)ch * BB * CC * FF + idx];
    V[idx] = s;
}

// ---------------- GCN ------------------------------------------------------
__global__ void k_nodes(const int* __restrict__ nodes, const float* __restrict__ emb,
                        float* __restrict__ xn) {
    size_t idx = (size_t)blockIdx.x * 256 + threadIdx.x;
    if (idx >= (size_t)BB * NN * DD) return;
    int d = (int)(idx & (DD - 1));
    size_t row = idx >> 8;
    xn[idx] = emb[(size_t)nodes[row] * DD + d];
}

__global__ void k_deginit(int* __restrict__ deg) {
    int idx = blockIdx.x * 256 + threadIdx.x;
    if (idx < BB * NN) deg[idx] = 1;   // self loop
}

__global__ void k_degadd(const int* __restrict__ edges, int* __restrict__ deg) {
    int idx = blockIdx.x * 256 + threadIdx.x;
    if (idx >= BB * EE) return;
    int b = idx / EE, e = idx % EE;
    int dst = edges[(b * 2 + 1) * EE + e];
    atomicAdd(&deg[b * NN + dst], 1);
}

__global__ void k_dinv(const int* __restrict__ deg, float* __restrict__ dinv) {
    int idx = blockIdx.x * 256 + threadIdx.x;
    if (idx < BB * NN) dinv[idx] = rsqrtf((float)deg[idx]);
}

// out[b][n][o] = sum_i A[b][n][i] * W[o][i]   (64x64 tile, 256 thr, 4x4/thr)
__global__ void k_gemm(const float* __restrict__ A, const float* __restrict__ W,
                       float* __restrict__ out) {
    __shared__ float s_a[64][33];
    __shared__ float s_b[64][33];
    int o0 = blockIdx.x * 64, n0 = blockIdx.y * 64, b = blockIdx.z;
    int tid = threadIdx.x;                 // 256 threads
    int ot = tid >> 4, nt = tid & 15;      // 16 x 16 -> 64 x 64
    float acc[4][4];
#pragma unroll
    for (int u = 0; u < 4; u++)
#pragma unroll
        for (int v = 0; v < 4; v++) acc[u][v] = 0.f;
    for (int i0 = 0; i0 < DD; i0 += 32) {
        __syncthreads();
        for (int idx = tid; idx < 64 * 32; idx += 256) {
            int row = idx >> 5, ii = idx & 31;
            s_a[row][ii] = A[((size_t)b * NN + n0 + row) * DD + i0 + ii];
            s_b[row][ii] = W[(size_t)(o0 + row) * DD + i0 + ii];
        }
        __syncthreads();
#pragma unroll 4
        for (int ii = 0; ii < 32; ii++) {
            float wv[4], av[4];
#pragma unroll
            for (int u = 0; u < 4; u++) wv[u] = s_b[ot * 4 + u][ii];
#pragma unroll
            for (int v = 0; v < 4; v++) av[v] = s_a[nt * 4 + v][ii];
#pragma unroll
            for (int u = 0; u < 4; u++)
#pragma unroll
                for (int v = 0; v < 4; v++) acc[u][v] += wv[u] * av[v];
        }
    }
#pragma unroll
    for (int v = 0; v < 4; v++)
#pragma unroll
        for (int u = 0; u < 4; u++)
            out[((size_t)b * NN + n0 + nt * 4 + v) * DD + o0 + ot * 4 + u] = acc[u][v];
}

__global__ void k_self(const float* __restrict__ xw, const float* __restrict__ dinv,
                       float* __restrict__ out, int rows) {
    size_t idx = (size_t)blockIdx.x * 256 + threadIdx.x;
    if (idx >= (size_t)BB * rows * DD) return;
    int o = (int)(idx & (DD - 1));
    size_t row = idx >> 8;
    int b = (int)(row / rows);
    int n = (int)(row % rows);
    float di = dinv[b * NN + n];
    out[idx] = di * di * xw[((size_t)b * NN + n) * DD + o];
}

__global__ void k_edge(const int* __restrict__ edges, const float* __restrict__ dinv,
                       const float* __restrict__ xw, float* __restrict__ out,
                       int dstmax) {
    int b = blockIdx.y;
    int eloc = threadIdx.x >> 5, lane = threadIdx.x & 31;
    int e = blockIdx.x * 8 + eloc;
    int src = edges[(b * 2) * EE + e];
    int dst = edges[(b * 2 + 1) * EE + e];
    if (dst >= dstmax) return;
    float norm = dinv[b * NN + src] * dinv[b * NN + dst];
    const float* xr = xw + ((size_t)b * NN + src) * DD;
    float* orow = out + ((size_t)b * dstmax + dst) * DD;
#pragma unroll
    for (int j = 0; j < 8; j++) {
        int o = lane + j * 32;
        atomicAdd(&orow[o], norm * xr[o]);
    }
}

__global__ void k_post(float* __restrict__ buf, const float* __restrict__ bias,
                       int rows, int dorelu) {
    size_t idx = (size_t)blockIdx.x * 256 + threadIdx.x;
    if (idx >= (size_t)BB * rows * DD) return;
    int o = (int)(idx & (DD - 1));
    float v = buf[idx] + bias[o];
    if (dorelu) v = fmaxf(v, 0.f);
    buf[idx] = v;
}

// ---------------- final MLP --------------------------------------------------
__global__ void k_prepf1(const float* __restrict__ w, float* __restrict__ wT) {
    int idx = blockIdx.x * 256 + threadIdx.x;
    if (idx >= FEAT * FFNH) return;
    int h = idx & (FFNH - 1), k = idx >> 7;
    wT[idx] = w[h * FEAT + k];
}

__global__ void k_final(const float* __restrict__ gout, const float* __restrict__ V,
                        const float* __restrict__ f1T, const float* __restrict__ f1b,
                        const float* __restrict__ f2w, const float* __restrict__ f2b,
                        float* __restrict__ y) {
    __shared__ float s_feat[FEAT];
    __shared__ float s_red[FFNH];
    int c = blockIdx.x, b = blockIdx.y, h = threadIdx.x;   // 128 threads
    for (int idx = h; idx < FEAT; idx += FFNH) {
        float v;
        if (idx < DD) {
            v = gout[((size_t)b * CC + c) * DD + idx];
        } else {
            int br = (idx - DD) / FF;
            int f  = (idx - DD) % FF;
            v = V[(((size_t)br * BB + b) * CC + c) * FF + f];
        }
        s_feat[idx] = v;
    }
    __syncthreads();
    float acc = f1b[h];
    for (int k = 0; k < FEAT; k++) acc += f1T[k * FFNH + h] * s_feat[k];
    float hid = fmaxf(acc, 0.f);
    s_red[h] = f2w[c * FFNH + h] * hid;
    __syncthreads();
    for (int s = 64; s > 0; s >>= 1) {
        if (h < s) s_red[h] += s_red[h + s];
        __syncthreads();
    }
    if (h == 0) y[b * CC + c] = s_red[0] + f2b[c];
}

// ---------------- branch driver ---------------------------------------------
template<int K>
static void run_branch(const float* cw, const float* cb, const float* rw,
                       const float* bn_g, const float* bn_b,
                       const float* aw, const float* au,
                       float* buf, int br) {
    float* h    = buf + OFF_H;
    float* t0   = buf + OFF_T0;
    float* t1   = buf + OFF_T1;
    float* Z    = buf + OFF_Z;
    float* lg   = buf + OFF_LOG;
    float* rmax = buf + OFF_RMAX;
    float* rsin = buf + OFF_RSINV;
    float* vp   = buf + OFF_VPART;
    float* V    = buf + OFF_V + (size_t)br * BB * CC * FF;
    float* wA   = buf + OFF_WA;
    float* wB   = buf + OFF_WB;

    dim3 cgrid(LL / 128, BB);
    k_prepw<<<(K * DD * FP + 255) / 256, 256>>>(cw, wA, K, DD, DD);
    k_conv_mma<K, DD><<<cgrid, 256>>>(h, wA, cb, bn_g, bn_b, nullptr, t0, 0);
    k_prepw<<<(K * FP * FP + 255) / 256, 256>>>(rw, wB, K, FF, FP);
    k_conv_mma<K, FP><<<cgrid, 256>>>(t0, wB, nullptr, bn_g + FF, bn_b + FF, t0, t1, 1);
    k_prepw<<<(K * FP * FP + 255) / 256, 256>>>(rw + (size_t)FF * FF * K, wB, K, FF, FP);
    k_conv_mma<K, FP><<<cgrid, 256>>>(t1, wB, nullptr, bn_g + 2 * FF, bn_b + 2 * FF, t1, t0, 1);

    k_z<<<dim3(AA / 32, LL / 64, BB), 128>>>(t0, aw, Z);
    k_logits<<<dim3(LL / 256, BB), 256>>>(Z, au, lg);
    k_soft<<<dim3(CC, BB), 256>>>(lg, rmax, rsin);
    k_v<<<dim3(2, 16, BB), 128>>>(t0, lg, rmax, rsin, vp);
    k_vred<<<(BB * CC * FF + 255) / 256, 256>>>(vp, V);
}

extern "C" void kernel_launch(void* const* d_in, const int* in_sizes, int n_in,
                              void* d_out, int out_size) {
    const int*   x        = (const int*)d_in[0];
    const int*   nodes    = (const int*)d_in[2];
    const int*   edges    = (const int*)d_in[3];
    const float* word_emb = (const float*)d_in[4];
    const float* ent_emb  = (const float*)d_in[5];
    const float* convw3   = (const float*)d_in[6];
    const float* convb3   = (const float*)d_in[7];
    const float* resw3    = (const float*)d_in[8];
    const float* convw5   = (const float*)d_in[9];
    const float* convb5   = (const float*)d_in[10];
    const float* resw5    = (const float*)d_in[11];
    const float* convw9   = (const float*)d_in[12];
    const float* convb9   = (const float*)d_in[13];
    const float* resw9    = (const float*)d_in[14];
    const float* bn_gamma = (const float*)d_in[15];
    const float* bn_beta  = (const float*)d_in[16];
    const float* attn_w   = (const float*)d_in[17];
    const float* attn_u   = (const float*)d_in[18];
    const float* gc1_w    = (const float*)d_in[19];
    const float* gc1_b    = (const float*)d_in[20];
    const float* gc2_w    = (const float*)d_in[21];
    const float* gc2_b    = (const float*)d_in[22];
    const float* fin1_w   = (const float*)d_in[23];
    const float* fin1_b   = (const float*)d_in[24];
    const float* fin2_w   = (const float*)d_in[25];
    const float* fin2_b   = (const float*)d_in[26];
    float* out = (float*)d_out;

    float* buf; int* deg;
    cudaGetSymbolAddress((void**)&buf, g_buf);
    cudaGetSymbolAddress((void**)&deg, g_deg);

    // embedding
    k_embed<<<(int)(((size_t)BB * LL * DD + 255) / 256), 256>>>(x, word_emb, buf + OFF_H);

    // three encoder branches
    run_branch<3>(convw3, convb3, resw3, bn_gamma + 0 * 3 * FF, bn_beta + 0 * 3 * FF,
                  attn_w + 0 * AA * FF, attn_u + 0 * CC * AA, buf, 0);
    run_branch<5>(convw5, convb5, resw5, bn_gamma + 1 * 3 * FF, bn_beta + 1 * 3 * FF,
                  attn_w + 1 * AA * FF, attn_u + 1 * CC * AA, buf, 1);
    run_branch<9>(convw9, convb9, resw9, bn_gamma + 2 * 3 * FF, bn_beta + 2 * 3 * FF,
                  attn_w + 2 * AA * FF, attn_u + 2 * CC * AA, buf, 2);

    // GCN
    float* xn   = buf + OFF_XN;
    float* xw   = buf + OFF_XW;
    float* g1   = buf + OFF_G1;
    float* gout = buf + OFF_GOUT;
    float* dinv = buf + OFF_DINV;
    k_nodes<<<(int)(((size_t)BB * NN * DD + 255) / 256), 256>>>(nodes, ent_emb, xn);
    k_deginit<<<(BB * NN + 255) / 256, 256>>>(deg);
    k_degadd<<<(BB * EE + 255) / 256, 256>>>(edges, deg);
    k_dinv<<<(BB * NN + 255) / 256, 256>>>(deg, dinv);

    k_gemm<<<dim3(DD / 64, NN / 64, BB), 256>>>(xn, gc1_w, xw);
    k_self<<<(int)(((size_t)BB * NN * DD + 255) / 256), 256>>>(xw, dinv, g1, NN);
    k_edge<<<dim3(EE / 8, BB), 256>>>(edges, dinv, xw, g1, NN);
    k_post<<<(int)(((size_t)BB * NN * DD + 255) / 256), 256>>>(g1, gc1_b, NN, 1);

    k_gemm<<<dim3(DD / 64, NN / 64, BB), 256>>>(g1, gc2_w, xw);
    k_self<<<(int)(((size_t)BB * CC * DD + 255) / 256), 256>>>(xw, dinv, gout, CC);
    k_edge<<<dim3(EE / 8, BB), 256>>>(edges, dinv, xw, gout, CC);
    k_post<<<(int)(((size_t)BB * CC * DD + 255) / 256), 256>>>(gout, gc2_b, CC, 0);

    // final MLP
    k_prepf1<<<(FEAT * FFNH + 255) / 256, 256>>>(fin1_w, buf + OFF_F1T);
    k_final<<<dim3(CC, BB), FFNH>>>(gout, buf + OFF_V, buf + OFF_F1T,
                                    fin1_b, fin2_w, fin2_b, out);
}

// round 5
// speedup vs baseline: 2.0551x; 1.2313x over previous
#include <cuda_runtime.h>
#include <math.h>
#include <stdint.h>

#define BB   16
#define LL   4096
#define DD   256
#define CC   50
#define NN   512
#define EE   8192
#define FF   100
#define FP   128
#define AA   256
#define FFNH 128
#define FEAT 556   /* 256 + 3*100 */

// ---------------- one big static scratch buffer (no allocations) ------------
static constexpr size_t OFF_H     = 0;
static constexpr size_t OFF_T0    = OFF_H     + (size_t)BB*LL*DD;
static constexpr size_t OFF_T1    = OFF_T0    + (size_t)BB*LL*FP;
static constexpr size_t OFF_Z     = OFF_T1    + (size_t)BB*LL*FP;   /* [b][l][AA] */
static constexpr size_t OFF_LOG   = OFF_Z     + (size_t)BB*LL*AA;   /* [b][c][l] */
static constexpr size_t OFF_RMAX  = OFF_LOG   + (size_t)BB*CC*LL;
static constexpr size_t OFF_RSINV = OFF_RMAX  + (size_t)BB*CC;
static constexpr size_t OFF_VPART = OFF_RSINV + (size_t)BB*CC;
static constexpr size_t OFF_V     = OFF_VPART + (size_t)16*BB*CC*FF;
static constexpr size_t OFF_WA    = OFF_V     + (size_t)3*BB*CC*FF;   /* 3 x 9*DD*FP */
static constexpr size_t OFF_WB    = OFF_WA    + (size_t)3*9*DD*FP;    /* 6 x 9*FP*FP */
static constexpr size_t OFF_AWP   = OFF_WB    + (size_t)6*9*FP*FP;    /* 3 x FP*AA  */
static constexpr size_t OFF_AUP   = OFF_AWP   + (size_t)3*FP*AA;      /* 3 x AA*64  */
static constexpr size_t OFF_GWT   = OFF_AUP   + (size_t)3*AA*64;      /* 2 x DD*DD  */
static constexpr size_t OFF_XN    = OFF_GWT   + (size_t)2*DD*DD;
static constexpr size_t OFF_XW    = OFF_XN    + (size_t)BB*NN*DD;
static constexpr size_t OFF_G1    = OFF_XW    + (size_t)BB*NN*DD;
static constexpr size_t OFF_GOUT  = OFF_G1    + (size_t)BB*NN*DD;
static constexpr size_t OFF_F1T   = OFF_GOUT  + (size_t)BB*CC*DD;
static constexpr size_t OFF_DINV  = OFF_F1T   + (size_t)FEAT*FFNH;
static constexpr size_t BUF_TOTAL = OFF_DINV  + (size_t)BB*NN;

__device__ float g_buf[BUF_TOTAL];
__device__ int   g_deg[BB*NN];

// ---------------- helpers ----------------------------------------------------
__device__ __forceinline__ float to_tf32(float x) {
    float r;
    asm("cvt.rna.tf32.f32 %0, %1;" : "=f"(r) : "f"(x));
    return r;
}

__device__ __forceinline__ void mma8(float d[4], const uint32_t a[4],
                                     uint32_t b0, uint32_t b1) {
    asm volatile(
        "mma.sync.aligned.m16n8k8.row.col.f32.tf32.tf32.f32 "
        "{%0,%1,%2,%3}, {%4,%5,%6,%7}, {%8,%9}, {%0,%1,%2,%3};\n"
        : "+f"(d[0]), "+f"(d[1]), "+f"(d[2]), "+f"(d[3])
        : "r"(a[0]), "r"(a[1]), "r"(a[2]), "r"(a[3]), "r"(b0), "r"(b1));
}

// ---------------- embedding gather  h[b][l][d] ------------------------------
__global__ void k_embed(const int* __restrict__ x, const float* __restrict__ emb,
                        float* __restrict__ h) {
    size_t idx = (size_t)blockIdx.x * 256 + threadIdx.x;
    if (idx >= (size_t)BB*LL*DD) return;
    int d = (int)(idx & (DD - 1));
    size_t row = idx >> 8;
    h[idx] = emb[(size_t)x[row] * DD + d];
}

// ---- conv weight transpose/pad (+tf32 round): w[F][CIN][K] -> wT[K][CINP][FP]
__global__ void k_prepw(const float* __restrict__ w, float* __restrict__ wT,
                        int K, int CIN, int CINP) {
    int idx = blockIdx.x * 256 + threadIdx.x;
    int tot = K * CINP * FP;
    if (idx >= tot) return;
    int f = idx & 127;
    int rem = idx >> 7;
    int d = rem % CINP;
    int k = rem / CINP;
    wT[idx] = (f < FF && d < CIN) ? to_tf32(w[(f * CIN + d) * K + k]) : 0.f;
}

// ---- generic B transpose/pad (+tf32): B[n][k] -> Bt[k][n], zero-padded -----
__global__ void k_prep_bt(const float* __restrict__ B, float* __restrict__ Bt,
                          int NOUT, int CIN, int NOUTP, int CINP) {
    int idx = blockIdx.x * 256 + threadIdx.x;
    if (idx >= CINP * NOUTP) return;
    int n = idx % NOUTP, k = idx / NOUTP;
    Bt[idx] = (n < NOUT && k < CIN) ? to_tf32(B[(size_t)n * CIN + k]) : 0.f;
}

// ---------------- conv1d 'same' via tf32 mma, double-buffered weights -------
// in:[B][L][CINP]  wT:[K][CINP][FP] (pre-tf32)  out:[B][L][FP] (f>=FF zero)
// mode 0: out = tanh(acc + cb[f])*sc + bt
// mode 1: out = tanh(acc*sc + bt + resid[b][l][f])
template<int K, int CINP>
__global__ void __launch_bounds__(256, 2)
k_conv_mma(const float* __restrict__ in, const float* __restrict__ wT,
           const float* __restrict__ cb, const float* __restrict__ gamma,
           const float* __restrict__ beta, const float* __restrict__ resid,
           float* __restrict__ out, int mode) {
    constexpr int LT = 128;
    constexpr int PAD = K / 2;
    constexpr int ROWS = LT + K - 1;
    constexpr int ISTR = 36;    // bank = (4*row + col) & 31 -> conflict-free A frags
    constexpr int WSTR = 136;   // bank = (8*row + col) & 31 -> conflict-free B frags
    constexpr int WTILE = 32 * WSTR;
    extern __shared__ float smem[];
    float* s_in = smem;                 // ROWS*ISTR
    float* s_w  = smem + ROWS * ISTR;   // 2 * WTILE

    int b = blockIdx.y, l0 = blockIdx.x * LT, tid = threadIdx.x;
    int wid = tid >> 5, lane = tid & 31;
    int wl = wid >> 1, wf = wid & 1;      // 4 L-warps x 2 F-warps
    int grp = lane >> 2, thr = lane & 3;

    float acc[2][8][4];
#pragma unroll
    for (int mi = 0; mi < 2; mi++)
#pragma unroll
        for (int ni = 0; ni < 8; ni++)
#pragma unroll
            for (int ci = 0; ci < 4; ci++) acc[mi][ni][ci] = 0.f;

    const float* inb = in + (size_t)b * LL * CINP;

    for (int d0 = 0; d0 < CINP; d0 += 32) {
        // trailing sync of previous iteration protects reuse
        for (int t = tid; t < ROWS * 32; t += 256) {
            int row = t >> 5, dd = t & 31;
            int gl = l0 - PAD + row;
            float v = (gl >= 0 && gl < LL) ? inb[(size_t)gl * CINP + d0 + dd] : 0.f;
            s_in[row * ISTR + dd] = to_tf32(v);
        }
        {
            const float* wk = wT + (size_t)d0 * FP;   // k = 0
            for (int t = tid; t < 32 * FP; t += 256) {
                int dd = t >> 7, f = t & 127;
                s_w[dd * WSTR + f] = wk[dd * FP + f];
            }
        }
        __syncthreads();
#pragma unroll
        for (int k = 0; k < K; k++) {
            if (k + 1 < K) {
                const float* wk = wT + ((size_t)(k + 1) * CINP + d0) * FP;
                float* dstw = s_w + ((k + 1) & 1) * WTILE;
                for (int t = tid; t < 32 * FP; t += 256) {
                    int dd = t >> 7, f = t & 127;
                    dstw[dd * WSTR + f] = wk[dd * FP + f];
                }
            }
            const float* curw = s_w + (k & 1) * WTILE;
#pragma unroll
            for (int ds = 0; ds < 32; ds += 8) {
                uint32_t a[2][4];
#pragma unroll
                for (int mi = 0; mi < 2; mi++) {
                    int r0 = wl * 32 + mi * 16 + grp + k;
                    a[mi][0] = __float_as_uint(s_in[r0 * ISTR + ds + thr]);
                    a[mi][1] = __float_as_uint(s_in[(r0 + 8) * ISTR + ds + thr]);
                    a[mi][2] = __float_as_uint(s_in[r0 * ISTR + ds + thr + 4]);
                    a[mi][3] = __float_as_uint(s_in[(r0 + 8) * ISTR + ds + thr + 4]);
                }
#pragma unroll
                for (int ni = 0; ni < 8; ni++) {
                    int f = wf * 64 + ni * 8 + grp;
                    uint32_t b0 = __float_as_uint(curw[(ds + thr) * WSTR + f]);
                    uint32_t b1 = __float_as_uint(curw[(ds + thr + 4) * WSTR + f]);
                    mma8(acc[0][ni], a[0], b0, b1);
                    mma8(acc[1][ni], a[1], b0, b1);
                }
            }
            __syncthreads();
        }
    }

    const float BNI = rsqrtf(1.f + 1e-5f);
#pragma unroll
    for (int mi = 0; mi < 2; mi++) {
#pragma unroll
        for (int ci = 0; ci < 4; ci++) {
            int l = l0 + wl * 32 + mi * 16 + grp + ((ci >= 2) ? 8 : 0);
            size_t base = ((size_t)b * LL + l) * FP;
#pragma unroll
            for (int ni = 0; ni < 8; ni++) {
                int f = wf * 64 + ni * 8 + 2 * thr + (ci & 1);
                float v = acc[mi][ni][ci];
                float o;
                if (f < FF) {
                    float sc = gamma[f] * BNI, bt = beta[f];
                    if (mode == 0) o = tanhf(v + cb[f]) * sc + bt;
                    else           o = tanhf(v * sc + bt + resid[base + f]);
                } else {
                    o = 0.f;
                }
                out[base + f] = o;
            }
        }
    }
}

template<int K, int CINP>
constexpr int conv_smem_bytes() {
    return ((128 + K - 1) * 36 + 2 * 32 * 136) * 4;
}

// ---------------- generic tf32 NT GEMM: out[m][n] = A[m][k]*Bt[k][n] --------
// A: fp32 [rows][CINP], Bt pre-tf32 [CINP][nstride].
// TRANSOUT: out[(n)*LL + m] for n<cclamp.  TANH: tanh epilogue.
template<int CINP, int WF, bool TANH, bool TRANSOUT>
__global__ void k_mma_nt(const float* __restrict__ A, const float* __restrict__ Bt,
                         float* __restrict__ out, int nstride,
                         size_t a_bstr, size_t o_bstr, int ostr, int cclamp) {
    constexpr int NT = WF * 128;           // threads
    constexpr int WIDTH = WF * 64;         // n-tile
    constexpr int WSTR = WIDTH + 8;
    __shared__ float s_a[128 * 36];
    __shared__ float s_w[32 * WSTR];
    int b = blockIdx.z;
    int m0 = blockIdx.x * 128;
    int n0 = blockIdx.y * WIDTH;
    A += (size_t)b * a_bstr;
    out += (size_t)b * o_bstr;
    int tid = threadIdx.x;
    int wid = tid >> 5, lane = tid & 31;
    int wl = wid / WF, wf = wid % WF;
    int grp = lane >> 2, thr = lane & 3;

    float acc[2][8][4];
#pragma unroll
    for (int mi = 0; mi < 2; mi++)
#pragma unroll
        for (int ni = 0; ni < 8; ni++)
#pragma unroll
            for (int ci = 0; ci < 4; ci++) acc[mi][ni][ci] = 0.f;

    for (int k0 = 0; k0 < CINP; k0 += 32) {
        __syncthreads();
        for (int t = tid; t < 128 * 32; t += NT) {
            int row = t >> 5, dd = t & 31;
            s_a[row * 36 + dd] = to_tf32(A[(size_t)(m0 + row) * CINP + k0 + dd]);
        }
        for (int t = tid; t < 32 * WIDTH; t += NT) {
            int dd = t / WIDTH, f = t % WIDTH;
            s_w[dd * WSTR + f] = Bt[(size_t)(k0 + dd) * nstride + n0 + f];
        }
        __syncthreads();
#pragma unroll
        for (int ds = 0; ds < 32; ds += 8) {
            uint32_t a[2][4];
#pragma unroll
            for (int mi = 0; mi < 2; mi++) {
                int r0 = wl * 32 + mi * 16 + grp;
                a[mi][0] = __float_as_uint(s_a[r0 * 36 + ds + thr]);
                a[mi][1] = __float_as_uint(s_a[(r0 + 8) * 36 + ds + thr]);
                a[mi][2] = __float_as_uint(s_a[r0 * 36 + ds + thr + 4]);
                a[mi][3] = __float_as_uint(s_a[(r0 + 8) * 36 + ds + thr + 4]);
            }
#pragma unroll
            for (int ni = 0; ni < 8; ni++) {
                int f = wf * 64 + ni * 8 + grp;
                uint32_t b0 = __float_as_uint(s_w[(ds + thr) * WSTR + f]);
                uint32_t b1 = __float_as_uint(s_w[(ds + thr + 4) * WSTR + f]);
                mma8(acc[0][ni], a[0], b0, b1);
                mma8(acc[1][ni], a[1], b0, b1);
            }
        }
    }

#pragma unroll
    for (int mi = 0; mi < 2; mi++) {
#pragma unroll
        for (int ci = 0; ci < 4; ci++) {
            int mrow = wl * 32 + mi * 16 + grp + ((ci >= 2) ? 8 : 0);
#pragma unroll
            for (int ni = 0; ni < 8; ni++) {
                int n = wf * 64 + ni * 8 + 2 * thr + (ci & 1);
                float v = acc[mi][ni][ci];
                if (TANH) v = tanhf(v);
                if (TRANSOUT) {
                    int c = n0 + n;
                    if (c < cclamp) out[(size_t)c * LL + m0 + mrow] = v;
                } else {
                    out[(size_t)(m0 + mrow) * ostr + n0 + n] = v;
                }
            }
        }
    }
}

// ---------------- softmax stats per (b,c) row of length L -------------------
__global__ void k_soft(const float* __restrict__ logits, float* __restrict__ rmax,
                       float* __restrict__ rsinv) {
    __shared__ float sred[256];
    int c = blockIdx.x, b = blockIdx.y, tid = threadIdx.x;
    const float* row = logits + ((size_t)b * CC + c) * LL;
    float m = -1e30f;
    for (int l = tid; l < LL; l += 256) m = fmaxf(m, row[l]);
    sred[tid] = m; __syncthreads();
    for (int s = 128; s > 0; s >>= 1) {
        if (tid < s) sred[tid] = fmaxf(sred[tid], sred[tid + s]);
        __syncthreads();
    }
    m = sred[0]; __syncthreads();
    float sum = 0.f;
    for (int l = tid; l < LL; l += 256) sum += expf(row[l] - m);
    sred[tid] = sum; __syncthreads();
    for (int s = 128; s > 0; s >>= 1) {
        if (tid < s) sred[tid] += sred[tid + s];
        __syncthreads();
    }
    if (tid == 0) { rmax[b * CC + c] = m; rsinv[b * CC + c] = 1.f / sred[0]; }
}

// ---------------- V partials: vpart[chunk][b][c][f] -------------------------
__global__ void k_v(const float* __restrict__ t, const float* __restrict__ logits,
                    const float* __restrict__ rmax, const float* __restrict__ rsinv,
                    float* __restrict__ vpart) {
    __shared__ float s_w[25][256];
    int cgrp = blockIdx.x, chunk = blockIdx.y, b = blockIdx.z;
    int tid = threadIdx.x;                 // 128 threads
    int l0 = chunk * 256;
    for (int idx = tid; idx < 25 * 256; idx += 128) {
        int cl = idx >> 8, ll = idx & 255;
        int c = cgrp * 25 + cl;
        float m = rmax[b * CC + c], si = rsinv[b * CC + c];
        s_w[cl][ll] = expf(logits[((size_t)b * CC + c) * LL + l0 + ll] - m) * si;
    }
    __syncthreads();
    float acc[25];
#pragma unroll
    for (int c = 0; c < 25; c++) acc[c] = 0.f;
    int f = tid;
    for (int ll = 0; ll < 256; ll++) {
        float tv = (f < FF) ? t[((size_t)b * LL + l0 + ll) * FP + f] : 0.f;
#pragma unroll
        for (int c = 0; c < 25; c++) acc[c] += s_w[c][ll] * tv;
    }
    if (f < FF) {
#pragma unroll
        for (int c = 0; c < 25; c++) {
            int cg = cgrp * 25 + c;
            vpart[(((size_t)chunk * BB + b) * CC + cg) * FF + f] = acc[c];
        }
    }
}

__global__ void k_vred(const float* __restrict__ vpart, float* __restrict__ V) {
    int idx = blockIdx.x * 256 + threadIdx.x;
    if (idx >= BB * CC * FF) return;
    float s = 0.f;
#pragma unroll
    for (int ch = 0; ch < 16; ch++) s += vpart[(size_t)ch * BB * CC * FF + idx];
    V[idx] = s;
}

// ---------------- GCN ------------------------------------------------------
__global__ void k_nodes(const int* __restrict__ nodes, const float* __restrict__ emb,
                        float* __restrict__ xn) {
    size_t idx = (size_t)blockIdx.x * 256 + threadIdx.x;
    if (idx >= (size_t)BB * NN * DD) return;
    int d = (int)(idx & (DD - 1));
    size_t row = idx >> 8;
    xn[idx] = emb[(size_t)nodes[row] * DD + d];
}

__global__ void k_deginit(int* __restrict__ deg) {
    int idx = blockIdx.x * 256 + threadIdx.x;
    if (idx < BB * NN) deg[idx] = 1;   // self loop
}

__global__ void k_degadd(const int* __restrict__ edges, int* __restrict__ deg) {
    int idx = blockIdx.x * 256 + threadIdx.x;
    if (idx >= BB * EE) return;
    int b = idx / EE, e = idx % EE;
    int dst = edges[(b * 2 + 1) * EE + e];
    atomicAdd(&deg[b * NN + dst], 1);
}

__global__ void k_dinv(const int* __restrict__ deg, float* __restrict__ dinv) {
    int idx = blockIdx.x * 256 + threadIdx.x;
    if (idx < BB * NN) dinv[idx] = rsqrtf((float)deg[idx]);
}

__global__ void k_self(const float* __restrict__ xw, const float* __restrict__ dinv,
                       float* __restrict__ out, int rows) {
    size_t idx = (size_t)blockIdx.x * 256 + threadIdx.x;
    if (idx >= (size_t)BB * rows * DD) return;
    int o = (int)(idx & (DD - 1));
    size_t row = idx >> 8;
    int b = (int)(row / rows);
    int n = (int)(row % rows);
    float di = dinv[b * NN + n];
    out[idx] = di * di * xw[((size_t)b * NN + n) * DD + o];
}

__global__ void k_edge(const int* __restrict__ edges, const float* __restrict__ dinv,
                       const float* __restrict__ xw, float* __restrict__ out,
                       int dstmax) {
    int b = blockIdx.y;
    int eloc = threadIdx.x >> 5, lane = threadIdx.x & 31;
    int e = blockIdx.x * 8 + eloc;
    int src = edges[(b * 2) * EE + e];
    int dst = edges[(b * 2 + 1) * EE + e];
    if (dst >= dstmax) return;
    float norm = dinv[b * NN + src] * dinv[b * NN + dst];
    const float* xr = xw + ((size_t)b * NN + src) * DD;
    float* orow = out + ((size_t)b * dstmax + dst) * DD;
#pragma unroll
    for (int j = 0; j < 8; j++) {
        int o = lane + j * 32;
        atomicAdd(&orow[o], norm * xr[o]);
    }
}

__global__ void k_post(float* __restrict__ buf, const float* __restrict__ bias,
                       int rows, int dorelu) {
    size_t idx = (size_t)blockIdx.x * 256 + threadIdx.x;
    if (idx >= (size_t)BB * rows * DD) return;
    int o = (int)(idx & (DD - 1));
    float v = buf[idx] + bias[o];
    if (dorelu) v = fmaxf(v, 0.f);
    buf[idx] = v;
}

// ---------------- final MLP --------------------------------------------------
__global__ void k_prepf1(const float* __restrict__ w, float* __restrict__ wT) {
    int idx = blockIdx.x * 256 + threadIdx.x;
    if (idx >= FEAT * FFNH) return;
    int h = idx & (FFNH - 1), k = idx >> 7;
    wT[idx] = w[h * FEAT + k];
}

__global__ void k_final(const float* __restrict__ gout, const float* __restrict__ V,
                        const float* __restrict__ f1T, const float* __restrict__ f1b,
                        const float* __restrict__ f2w, const float* __restrict__ f2b,
                        float* __restrict__ y) {
    __shared__ float s_feat[FEAT];
    __shared__ float s_red[FFNH];
    int c = blockIdx.x, b = blockIdx.y, h = threadIdx.x;   // 128 threads
    for (int idx = h; idx < FEAT; idx += FFNH) {
        float v;
        if (idx < DD) {
            v = gout[((size_t)b * CC + c) * DD + idx];
        } else {
            int br = (idx - DD) / FF;
            int f  = (idx - DD) % FF;
            v = V[(((size_t)br * BB + b) * CC + c) * FF + f];
        }
        s_feat[idx] = v;
    }
    __syncthreads();
    float acc = f1b[h];
    for (int k = 0; k < FEAT; k++) acc += f1T[k * FFNH + h] * s_feat[k];
    float hid = fmaxf(acc, 0.f);
    s_red[h] = f2w[c * FFNH + h] * hid;
    __syncthreads();
    for (int s = 64; s > 0; s >>= 1) {
        if (h < s) s_red[h] += s_red[h + s];
        __syncthreads();
    }
    if (h == 0) y[b * CC + c] = s_red[0] + f2b[c];
}

// ---------------- branch driver ---------------------------------------------
// br: output slot AND parameter index (0:K=3, 1:K=5, 2:K=9)
template<int K>
static void run_branch(const float* cw, const float* cb, const float* rw,
                       const float* bn_g, const float* bn_b,
                       const float* aw, const float* au,
                       float* buf, int br) {
    float* h    = buf + OFF_H;
    float* t0   = buf + OFF_T0;
    float* t1   = buf + OFF_T1;
    float* Z    = buf + OFF_Z;
    float* lg   = buf + OFF_LOG;
    float* rmax = buf + OFF_RMAX;
    float* rsin = buf + OFF_RSINV;
    float* vp   = buf + OFF_VPART;
    float* V    = buf + OFF_V + (size_t)br * BB * CC * FF;
    float* wA   = buf + OFF_WA + (size_t)br * 9 * DD * FP;
    float* wB0  = buf + OFF_WB + (size_t)(br * 2 + 0) * 9 * FP * FP;
    float* wB1  = buf + OFF_WB + (size_t)(br * 2 + 1) * 9 * FP * FP;
    float* awp  = buf + OFF_AWP + (size_t)br * FP * AA;
    float* aup  = buf + OFF_AUP + (size_t)br * AA * 64;

    cudaFuncSetAttribute(k_conv_mma<K, DD>, cudaFuncAttributeMaxDynamicSharedMemorySize,
                         conv_smem_bytes<K, DD>());
    cudaFuncSetAttribute(k_conv_mma<K, FP>, cudaFuncAttributeMaxDynamicSharedMemorySize,
                         conv_smem_bytes<K, FP>());

    dim3 cgrid(LL / 128, BB);
    // preps first (so for the first branch, launch #6 overall = big conv)
    k_prepw<<<(K * DD * FP + 255) / 256, 256>>>(cw, wA, K, DD, DD);
    k_prepw<<<(K * FP * FP + 255) / 256, 256>>>(rw, wB0, K, FF, FP);
    k_prepw<<<(K * FP * FP + 255) / 256, 256>>>(rw + (size_t)FF * FF * K, wB1, K, FF, FP);
    k_prep_bt<<<(FP * AA + 255) / 256, 256>>>(aw, awp, AA, FF, AA, FP);

    k_conv_mma<K, DD><<<cgrid, 256, conv_smem_bytes<K, DD>()>>>(
        h, wA, cb, bn_g, bn_b, nullptr, t0, 0);
    k_conv_mma<K, FP><<<cgrid, 256, conv_smem_bytes<K, FP>()>>>(
        t0, wB0, nullptr, bn_g + FF, bn_b + FF, t0, t1, 1);
    k_conv_mma<K, FP><<<cgrid, 256, conv_smem_bytes<K, FP>()>>>(
        t1, wB1, nullptr, bn_g + 2 * FF, bn_b + 2 * FF, t1, t0, 1);

    // Z[b][l][a] = tanh(t0 . aw^T)
    k_mma_nt<FP, 2, true, false><<<dim3(LL / 128, AA / 128, BB), 256>>>(
        t0, awp, Z, AA, (size_t)LL * FP, (size_t)LL * AA, AA, 0);
    // logits[b][c][l] = Z . au^T (transposed store)
    k_prep_bt<<<(AA * 64 + 255) / 256, 256>>>(au, aup, CC, AA, 64, AA);
    k_mma_nt<AA, 1, false, true><<<dim3(LL / 128, 1, BB), 128>>>(
        Z, aup, lg, 64, (size_t)LL * AA, (size_t)CC * LL, 0, CC);

    k_soft<<<dim3(CC, BB), 256>>>(lg, rmax, rsin);
    k_v<<<dim3(2, 16, BB), 128>>>(t0, lg, rmax, rsin, vp);
    k_vred<<<(BB * CC * FF + 255) / 256, 256>>>(vp, V);
}

extern "C" void kernel_launch(void* const* d_in, const int* in_sizes, int n_in,
                              void* d_out, int out_size) {
    const int*   x        = (const int*)d_in[0];
    const int*   nodes    = (const int*)d_in[2];
    const int*   edges    = (const int*)d_in[3];
    const float* word_emb = (const float*)d_in[4];
    const float* ent_emb  = (const float*)d_in[5];
    const float* convw3   = (const float*)d_in[6];
    const float* convb3   = (const float*)d_in[7];
    const float* resw3    = (const float*)d_in[8];
    const float* convw5   = (const float*)d_in[9];
    const float* convb5   = (const float*)d_in[10];
    const float* resw5    = (const float*)d_in[11];
    const float* convw9   = (const float*)d_in[12];
    const float* convb9   = (const float*)d_in[13];
    const float* resw9    = (const float*)d_in[14];
    const float* bn_gamma = (const float*)d_in[15];
    const float* bn_beta  = (const float*)d_in[16];
    const float* attn_w   = (const float*)d_in[17];
    const float* attn_u   = (const float*)d_in[18];
    const float* gc1_w    = (const float*)d_in[19];
    const float* gc1_b    = (const float*)d_in[20];
    const float* gc2_w    = (const float*)d_in[21];
    const float* gc2_b    = (const float*)d_in[22];
    const float* fin1_w   = (const float*)d_in[23];
    const float* fin1_b   = (const float*)d_in[24];
    const float* fin2_w   = (const float*)d_in[25];
    const float* fin2_b   = (const float*)d_in[26];
    float* out = (float*)d_out;

    float* buf; int* deg;
    cudaGetSymbolAddress((void**)&buf, g_buf);
    cudaGetSymbolAddress((void**)&deg, g_deg);

    // 1: embedding
    k_embed<<<(int)(((size_t)BB * LL * DD + 255) / 256), 256>>>(x, word_emb, buf + OFF_H);

    // K=9 branch FIRST: launches 2-5 are preps, launch 6 = k_conv_mma<9,DD> (profiled)
    run_branch<9>(convw9, convb9, resw9, bn_gamma + 2 * 3 * FF, bn_beta + 2 * 3 * FF,
                  attn_w + 2 * AA * FF, attn_u + 2 * CC * AA, buf, 2);
    run_branch<3>(convw3, convb3, resw3, bn_gamma + 0 * 3 * FF, bn_beta + 0 * 3 * FF,
                  attn_w + 0 * AA * FF, attn_u + 0 * CC * AA, buf, 0);
    run_branch<5>(convw5, convb5, resw5, bn_gamma + 1 * 3 * FF, bn_beta + 1 * 3 * FF,
                  attn_w + 1 * AA * FF, attn_u + 1 * CC * AA, buf, 1);

    // GCN
    float* xn   = buf + OFF_XN;
    float* xw   = buf + OFF_XW;
    float* g1   = buf + OFF_G1;
    float* gout = buf + OFF_GOUT;
    float* dinv = buf + OFF_DINV;
    float* gwt1 = buf + OFF_GWT;
    float* gwt2 = buf + OFF_GWT + (size_t)DD * DD;
    k_nodes<<<(int)(((size_t)BB * NN * DD + 255) / 256), 256>>>(nodes, ent_emb, xn);
    k_deginit<<<(BB * NN + 255) / 256, 256>>>(deg);
    k_degadd<<<(BB * EE + 255) / 256, 256>>>(edges, deg);
    k_dinv<<<(BB * NN + 255) / 256, 256>>>(deg, dinv);

    k_prep_bt<<<(DD * DD + 255) / 256, 256>>>(gc1_w, gwt1, DD, DD, DD, DD);
    k_mma_nt<DD, 2, false, false><<<dim3(NN / 128, DD / 128, BB), 256>>>(
        xn, gwt1, xw, DD, (size_t)NN * DD, (size_t)NN * DD, DD, 0);
    k_self<<<(int)(((size_t)BB * NN * DD + 255) / 256), 256>>>(xw, dinv, g1, NN);
    k_edge<<<dim3(EE / 8, BB), 256>>>(edges, dinv, xw, g1, NN);
    k_post<<<(int)(((size_t)BB * NN * DD + 255) / 256), 256>>>(g1, gc1_b, NN, 1);

    k_prep_bt<<<(DD * DD + 255) / 256, 256>>>(gc2_w, gwt2, DD, DD, DD, DD);
    k_mma_nt<DD, 2, false, false><<<dim3(NN / 128, DD / 128, BB), 256>>>(
        g1, gwt2, xw, DD, (size_t)NN * DD, (size_t)NN * DD, DD, 0);
    k_self<<<(int)(((size_t)BB * CC * DD + 255) / 256), 256>>>(xw, dinv, gout, CC);
    k_edge<<<dim3(EE / 8, BB), 256>>>(edges, dinv, xw, gout, CC);
    k_post<<<(int)(((size_t)BB * CC * DD + 255) / 256), 256>>>(gout, gc2_b, CC, 0);

    // final MLP
    k_prepf1<<<(FEAT * FFNH + 255) / 256, 256>>>(fin1_w, buf + OFF_F1T);
    k_final<<<dim3(CC, BB), FFNH>>>(gout, buf + OFF_V, buf + OFF_F1T,
                                    fin1_b, fin2_w, fin2_b, out);
}

// round 6
// speedup vs baseline: 3.0224x; 1.4706x over previous
#include <cuda_runtime.h>
#include <math.h>
#include <stdint.h>

#define BB   16
#define LL   4096
#define DD   256
#define CC   50
#define NN   512
#define EE   8192
#define FF   100
#define FP   128
#define AA   256
#define FFNH 128
#define FEAT 556   /* 256 + 3*100 */

// ---------------- one big static scratch buffer (no allocations) ------------
static constexpr size_t OFF_H     = 0;
static constexpr size_t OFF_T0    = OFF_H     + (size_t)BB*LL*DD;
static constexpr size_t OFF_T1    = OFF_T0    + (size_t)BB*LL*FP;
static constexpr size_t OFF_Z     = OFF_T1    + (size_t)BB*LL*FP;   /* [b][l][AA] */
static constexpr size_t OFF_LOG   = OFF_Z     + (size_t)BB*LL*AA;   /* [b][c][l] */
static constexpr size_t OFF_RMAX  = OFF_LOG   + (size_t)BB*CC*LL;
static constexpr size_t OFF_RSINV = OFF_RMAX  + (size_t)BB*CC;
static constexpr size_t OFF_VPART = OFF_RSINV + (size_t)BB*CC;
static constexpr size_t OFF_V     = OFF_VPART + (size_t)16*BB*CC*FF;
static constexpr size_t OFF_WA    = OFF_V     + (size_t)3*BB*CC*FF;   /* 3 x 9*DD*FP */
static constexpr size_t OFF_WB    = OFF_WA    + (size_t)3*9*DD*FP;    /* 6 x 9*FP*FP */
static constexpr size_t OFF_AWP   = OFF_WB    + (size_t)6*9*FP*FP;    /* 3 x FP*AA  */
static constexpr size_t OFF_AUP   = OFF_AWP   + (size_t)3*FP*AA;      /* 3 x AA*64  */
static constexpr size_t OFF_GWT   = OFF_AUP   + (size_t)3*AA*64;      /* 2 x DD*DD  */
static constexpr size_t OFF_XN    = OFF_GWT   + (size_t)2*DD*DD;
static constexpr size_t OFF_XW    = OFF_XN    + (size_t)BB*NN*DD;
static constexpr size_t OFF_G1    = OFF_XW    + (size_t)BB*NN*DD;
static constexpr size_t OFF_GOUT  = OFF_G1    + (size_t)BB*NN*DD;
static constexpr size_t OFF_F1T   = OFF_GOUT  + (size_t)BB*CC*DD;
static constexpr size_t OFF_DINV  = OFF_F1T   + (size_t)FEAT*FFNH;
static constexpr size_t BUF_TOTAL = OFF_DINV  + (size_t)BB*NN;

__device__ float g_buf[BUF_TOTAL];
__device__ int   g_deg[BB*NN];

// ---------------- helpers ----------------------------------------------------
__device__ __forceinline__ float to_tf32(float x) {
    float r;
    asm("cvt.rna.tf32.f32 %0, %1;" : "=f"(r) : "f"(x));
    return r;
}

__device__ __forceinline__ void mma8(float d[4], const uint32_t a[4],
                                     uint32_t b0, uint32_t b1) {
    asm volatile(
        "mma.sync.aligned.m16n8k8.row.col.f32.tf32.tf32.f32 "
        "{%0,%1,%2,%3}, {%4,%5,%6,%7}, {%8,%9}, {%0,%1,%2,%3};\n"
        : "+f"(d[0]), "+f"(d[1]), "+f"(d[2]), "+f"(d[3])
        : "r"(a[0]), "r"(a[1]), "r"(a[2]), "r"(a[3]), "r"(b0), "r"(b1));
}

// 16B async copy; pred=false -> zero-fill
__device__ __forceinline__ void cp16(float* dst_smem, const float* src, bool pred) {
    uint32_t d = (uint32_t)__cvta_generic_to_shared(dst_smem);
    int sz = pred ? 16 : 0;
    asm volatile("cp.async.cg.shared.global [%0], [%1], 16, %2;\n"
                 :: "r"(d), "l"(src), "r"(sz));
}
__device__ __forceinline__ void cp_commit() {
    asm volatile("cp.async.commit_group;\n");
}
__device__ __forceinline__ void cp_wait0() {
    asm volatile("cp.async.wait_group 0;\n");
}

// ---------------- embedding gather  h[b][l][d] (tf32-rounded) ----------------
__global__ void k_embed(const int* __restrict__ x, const float* __restrict__ emb,
                        float* __restrict__ h) {
    size_t idx = (size_t)blockIdx.x * 256 + threadIdx.x;
    if (idx >= (size_t)BB*LL*DD) return;
    int d = (int)(idx & (DD - 1));
    size_t row = idx >> 8;
    h[idx] = to_tf32(emb[(size_t)x[row] * DD + d]);
}

// ---- conv weight transpose/pad (+tf32 round): w[F][CIN][K] -> wT[K][CINP][FP]
__global__ void k_prepw(const float* __restrict__ w, float* __restrict__ wT,
                        int K, int CIN, int CINP) {
    int idx = blockIdx.x * 256 + threadIdx.x;
    int tot = K * CINP * FP;
    if (idx >= tot) return;
    int f = idx & 127;
    int rem = idx >> 7;
    int d = rem % CINP;
    int k = rem / CINP;
    wT[idx] = (f < FF && d < CIN) ? to_tf32(w[(f * CIN + d) * K + k]) : 0.f;
}

// ---- generic B transpose/pad (+tf32): B[n][k] -> Bt[k][n], zero-padded -----
__global__ void k_prep_bt(const float* __restrict__ B, float* __restrict__ Bt,
                          int NOUT, int CIN, int NOUTP, int CINP) {
    int idx = blockIdx.x * 256 + threadIdx.x;
    if (idx >= CINP * NOUTP) return;
    int n = idx % NOUTP, k = idx / NOUTP;
    Bt[idx] = (n < NOUT && k < CIN) ? to_tf32(B[(size_t)n * CIN + k]) : 0.f;
}

// ---------------- conv1d 'same' via tf32 mma, cp.async + dbuf weights -------
// in:[B][L][CINP] (pre-tf32)  wT:[K][CINP][FP] (pre-tf32)  out:[B][L][FP]
// mode 0: out = tanh(acc + cb[f])*sc + bt
// mode 1: out = tanh(acc*sc + bt + resid[b][l][f])
template<int K, int CINP>
__global__ void __launch_bounds__(256, 2)
k_conv_mma(const float* __restrict__ in, const float* __restrict__ wT,
           const float* __restrict__ cb, const float* __restrict__ gamma,
           const float* __restrict__ beta, const float* __restrict__ resid,
           float* __restrict__ out, int mode) {
    constexpr int LT = 128;
    constexpr int PAD = K / 2;
    constexpr int ROWS = LT + K - 1;
    constexpr int ISTR = 36;    // bank = (4*row + col) & 31 -> conflict-free A frags
    constexpr int WSTR = 136;   // bank = (8*row + col) & 31 -> conflict-free B frags
    constexpr int WTILE = 32 * WSTR;
    extern __shared__ float smem[];
    float* s_in = smem;                 // ROWS*ISTR
    float* s_w  = smem + ROWS * ISTR;   // 2 * WTILE

    int b = blockIdx.y, l0 = blockIdx.x * LT, tid = threadIdx.x;
    int wid = tid >> 5, lane = tid & 31;
    int wl = wid >> 1, wf = wid & 1;      // 4 L-warps x 2 F-warps
    int grp = lane >> 2, thr = lane & 3;

    float acc[2][8][4];
#pragma unroll
    for (int mi = 0; mi < 2; mi++)
#pragma unroll
        for (int ni = 0; ni < 8; ni++)
#pragma unroll
            for (int ci = 0; ci < 4; ci++) acc[mi][ni][ci] = 0.f;

    const float* inb = in + (size_t)b * LL * CINP;

    for (int d0 = 0; d0 < CINP; d0 += 32) {
        // async fill: input tile + tap-0 weights
        for (int t = tid; t < ROWS * 8; t += 256) {
            int row = t >> 3, seg = t & 7;
            int gl = l0 - PAD + row;
            cp16(&s_in[row * ISTR + seg * 4],
                 inb + (size_t)gl * CINP + d0 + seg * 4,
                 (gl >= 0 && gl < LL));
        }
        {
            const float* wk = wT + (size_t)d0 * FP;   // k = 0
            for (int t = tid; t < 32 * 32; t += 256) {
                int dd = t >> 5, seg = t & 31;
                cp16(&s_w[dd * WSTR + seg * 4], wk + dd * FP + seg * 4, true);
            }
        }
        cp_commit();
        cp_wait0();
        __syncthreads();
#pragma unroll
        for (int k = 0; k < K; k++) {
            if (k + 1 < K) {
                const float* wk = wT + ((size_t)(k + 1) * CINP + d0) * FP;
                float* dstw = s_w + ((k + 1) & 1) * WTILE;
                for (int t = tid; t < 32 * 32; t += 256) {
                    int dd = t >> 5, seg = t & 31;
                    cp16(&dstw[dd * WSTR + seg * 4], wk + dd * FP + seg * 4, true);
                }
                cp_commit();
            }
            const float* curw = s_w + (k & 1) * WTILE;
#pragma unroll
            for (int ds = 0; ds < 32; ds += 8) {
                uint32_t a[2][4];
#pragma unroll
                for (int mi = 0; mi < 2; mi++) {
                    int r0 = wl * 32 + mi * 16 + grp + k;
                    a[mi][0] = __float_as_uint(s_in[r0 * ISTR + ds + thr]);
                    a[mi][1] = __float_as_uint(s_in[(r0 + 8) * ISTR + ds + thr]);
                    a[mi][2] = __float_as_uint(s_in[r0 * ISTR + ds + thr + 4]);
                    a[mi][3] = __float_as_uint(s_in[(r0 + 8) * ISTR + ds + thr + 4]);
                }
#pragma unroll
                for (int ni = 0; ni < 8; ni++) {
                    int f = wf * 64 + ni * 8 + grp;
                    uint32_t b0 = __float_as_uint(curw[(ds + thr) * WSTR + f]);
                    uint32_t b1 = __float_as_uint(curw[(ds + thr + 4) * WSTR + f]);
                    mma8(acc[0][ni], a[0], b0, b1);
                    mma8(acc[1][ni], a[1], b0, b1);
                }
            }
            if (k + 1 < K) cp_wait0();
            __syncthreads();
        }
    }

    const float BNI = rsqrtf(1.f + 1e-5f);
#pragma unroll
    for (int mi = 0; mi < 2; mi++) {
#pragma unroll
        for (int ci = 0; ci < 4; ci++) {
            int l = l0 + wl * 32 + mi * 16 + grp + ((ci >= 2) ? 8 : 0);
            size_t base = ((size_t)b * LL + l) * FP;
#pragma unroll
            for (int ni = 0; ni < 8; ni++) {
                int f = wf * 64 + ni * 8 + 2 * thr + (ci & 1);
                float v = acc[mi][ni][ci];
                float o;
                if (f < FF) {
                    float sc = gamma[f] * BNI, bt = beta[f];
                    if (mode == 0) o = tanhf(v + cb[f]) * sc + bt;
                    else           o = tanhf(v * sc + bt + resid[base + f]);
                    o = to_tf32(o);
                } else {
                    o = 0.f;
                }
                out[base + f] = o;
            }
        }
    }
}

template<int K, int CINP>
constexpr int conv_smem_bytes() {
    return ((128 + K - 1) * 36 + 2 * 32 * 136) * 4;
}

// ---------------- generic tf32 NT GEMM: out[m][n] = A[m][k]*Bt[k][n] --------
// A: pre-tf32 fp32 [rows][CINP], Bt pre-tf32 [CINP][nstride].
// TRANSOUT: out[(n)*LL + m] for n<cclamp.  TANH: tanh epilogue (tf32-rounded).
template<int CINP, int WF, bool TANH, bool TRANSOUT>
__global__ void k_mma_nt(const float* __restrict__ A, const float* __restrict__ Bt,
                         float* __restrict__ out, int nstride,
                         size_t a_bstr, size_t o_bstr, int ostr, int cclamp) {
    constexpr int NT = WF * 128;           // threads
    constexpr int WIDTH = WF * 64;         // n-tile
    constexpr int WSTR = WIDTH + 8;
    __shared__ float s_a[128 * 36];
    __shared__ float s_w[32 * WSTR];
    int b = blockIdx.z;
    int m0 = blockIdx.x * 128;
    int n0 = blockIdx.y * WIDTH;
    A += (size_t)b * a_bstr;
    out += (size_t)b * o_bstr;
    int tid = threadIdx.x;
    int wid = tid >> 5, lane = tid & 31;
    int wl = wid / WF, wf = wid % WF;
    int grp = lane >> 2, thr = lane & 3;

    float acc[2][8][4];
#pragma unroll
    for (int mi = 0; mi < 2; mi++)
#pragma unroll
        for (int ni = 0; ni < 8; ni++)
#pragma unroll
            for (int ci = 0; ci < 4; ci++) acc[mi][ni][ci] = 0.f;

    for (int k0 = 0; k0 < CINP; k0 += 32) {
        __syncthreads();
        for (int t = tid; t < 128 * 8; t += NT) {
            int row = t >> 3, seg = t & 7;
            cp16(&s_a[row * 36 + seg * 4],
                 A + (size_t)(m0 + row) * CINP + k0 + seg * 4, true);
        }
        for (int t = tid; t < 32 * (WIDTH / 4); t += NT) {
            int dd = t / (WIDTH / 4), seg = t % (WIDTH / 4);
            cp16(&s_w[dd * WSTR + seg * 4],
                 Bt + (size_t)(k0 + dd) * nstride + n0 + seg * 4, true);
        }
        cp_commit();
        cp_wait0();
        __syncthreads();
#pragma unroll
        for (int ds = 0; ds < 32; ds += 8) {
            uint32_t a[2][4];
#pragma unroll
            for (int mi = 0; mi < 2; mi++) {
                int r0 = wl * 32 + mi * 16 + grp;
                a[mi][0] = __float_as_uint(s_a[r0 * 36 + ds + thr]);
                a[mi][1] = __float_as_uint(s_a[(r0 + 8) * 36 + ds + thr]);
                a[mi][2] = __float_as_uint(s_a[r0 * 36 + ds + thr + 4]);
                a[mi][3] = __float_as_uint(s_a[(r0 + 8) * 36 + ds + thr + 4]);
            }
#pragma unroll
            for (int ni = 0; ni < 8; ni++) {
                int f = wf * 64 + ni * 8 + grp;
                uint32_t b0 = __float_as_uint(s_w[(ds + thr) * WSTR + f]);
                uint32_t b1 = __float_as_uint(s_w[(ds + thr + 4) * WSTR + f]);
                mma8(acc[0][ni], a[0], b0, b1);
                mma8(acc[1][ni], a[1], b0, b1);
            }
        }
    }

#pragma unroll
    for (int mi = 0; mi < 2; mi++) {
#pragma unroll
        for (int ci = 0; ci < 4; ci++) {
            int mrow = wl * 32 + mi * 16 + grp + ((ci >= 2) ? 8 : 0);
#pragma unroll
            for (int ni = 0; ni < 8; ni++) {
                int n = wf * 64 + ni * 8 + 2 * thr + (ci & 1);
                float v = acc[mi][ni][ci];
                if (TANH) v = to_tf32(tanhf(v));
                if (TRANSOUT) {
                    int c = n0 + n;
                    if (c < cclamp) out[(size_t)c * LL + m0 + mrow] = v;
                } else {
                    out[(size_t)(m0 + mrow) * ostr + n0 + n] = v;
                }
            }
        }
    }
}

// ---------------- softmax stats per (b,c) row of length L -------------------
__global__ void k_soft(const float* __restrict__ logits, float* __restrict__ rmax,
                       float* __restrict__ rsinv) {
    __shared__ float sred[256];
    int c = blockIdx.x, b = blockIdx.y, tid = threadIdx.x;
    const float* row = logits + ((size_t)b * CC + c) * LL;
    float m = -1e30f;
    for (int l = tid; l < LL; l += 256) m = fmaxf(m, row[l]);
    sred[tid] = m; __syncthreads();
    for (int s = 128; s > 0; s >>= 1) {
        if (tid < s) sred[tid] = fmaxf(sred[tid], sred[tid + s]);
        __syncthreads();
    }
    m = sred[0]; __syncthreads();
    float sum = 0.f;
    for (int l = tid; l < LL; l += 256) sum += expf(row[l] - m);
    sred[tid] = sum; __syncthreads();
    for (int s = 128; s > 0; s >>= 1) {
        if (tid < s) sred[tid] += sred[tid + s];
        __syncthreads();
    }
    if (tid == 0) { rmax[b * CC + c] = m; rsinv[b * CC + c] = 1.f / sred[0]; }
}

// ---------------- V partials: vpart[chunk][b][c][f] -------------------------
__global__ void k_v(const float* __restrict__ t, const float* __restrict__ logits,
                    const float* __restrict__ rmax, const float* __restrict__ rsinv,
                    float* __restrict__ vpart) {
    __shared__ float s_w[25][256];
    int cgrp = blockIdx.x, chunk = blockIdx.y, b = blockIdx.z;
    int tid = threadIdx.x;                 // 128 threads
    int l0 = chunk * 256;
    for (int idx = tid; idx < 25 * 256; idx += 128) {
        int cl = idx >> 8, ll = idx & 255;
        int c = cgrp * 25 + cl;
        float m = rmax[b * CC + c], si = rsinv[b * CC + c];
        s_w[cl][ll] = expf(logits[((size_t)b * CC + c) * LL + l0 + ll] - m) * si;
    }
    __syncthreads();
    float acc[25];
#pragma unroll
    for (int c = 0; c < 25; c++) acc[c] = 0.f;
    int f = tid;
    for (int ll = 0; ll < 256; ll++) {
        float tv = (f < FF) ? t[((size_t)b * LL + l0 + ll) * FP + f] : 0.f;
#pragma unroll
        for (int c = 0; c < 25; c++) acc[c] += s_w[c][ll] * tv;
    }
    if (f < FF) {
#pragma unroll
        for (int c = 0; c < 25; c++) {
            int cg = cgrp * 25 + c;
            vpart[(((size_t)chunk * BB + b) * CC + cg) * FF + f] = acc[c];
        }
    }
}

__global__ void k_vred(const float* __restrict__ vpart, float* __restrict__ V) {
    int idx = blockIdx.x * 256 + threadIdx.x;
    if (idx >= BB * CC * FF) return;
    float s = 0.f;
#pragma unroll
    for (int ch = 0; ch < 16; ch++) s += vpart[(size_t)ch * BB * CC * FF + idx];
    V[idx] = s;
}

// ---------------- GCN ------------------------------------------------------
__global__ void k_nodes(const int* __restrict__ nodes, const float* __restrict__ emb,
                        float* __restrict__ xn) {
    size_t idx = (size_t)blockIdx.x * 256 + threadIdx.x;
    if (idx >= (size_t)BB * NN * DD) return;
    int d = (int)(idx & (DD - 1));
    size_t row = idx >> 8;
    xn[idx] = to_tf32(emb[(size_t)nodes[row] * DD + d]);
}

__global__ void k_deginit(int* __restrict__ deg) {
    int idx = blockIdx.x * 256 + threadIdx.x;
    if (idx < BB * NN) deg[idx] = 1;   // self loop
}

__global__ void k_degadd(const int* __restrict__ edges, int* __restrict__ deg) {
    int idx = blockIdx.x * 256 + threadIdx.x;
    if (idx >= BB * EE) return;
    int b = idx / EE, e = idx % EE;
    int dst = edges[(b * 2 + 1) * EE + e];
    atomicAdd(&deg[b * NN + dst], 1);
}

__global__ void k_dinv(const int* __restrict__ deg, float* __restrict__ dinv) {
    int idx = blockIdx.x * 256 + threadIdx.x;
    if (idx < BB * NN) dinv[idx] = rsqrtf((float)deg[idx]);
}

__global__ void k_self(const float* __restrict__ xw, const float* __restrict__ dinv,
                       float* __restrict__ out, int rows) {
    size_t idx = (size_t)blockIdx.x * 256 + threadIdx.x;
    if (idx >= (size_t)BB * rows * DD) return;
    int o = (int)(idx & (DD - 1));
    size_t row = idx >> 8;
    int b = (int)(row / rows);
    int n = (int)(row % rows);
    float di = dinv[b * NN + n];
    out[idx] = di * di * xw[((size_t)b * NN + n) * DD + o];
}

__global__ void k_edge(const int* __restrict__ edges, const float* __restrict__ dinv,
                       const float* __restrict__ xw, float* __restrict__ out,
                       int dstmax) {
    int b = blockIdx.y;
    int eloc = threadIdx.x >> 5, lane = threadIdx.x & 31;
    int e = blockIdx.x * 8 + eloc;
    int src = edges[(b * 2) * EE + e];
    int dst = edges[(b * 2 + 1) * EE + e];
    if (dst >= dstmax) return;
    float norm = dinv[b * NN + src] * dinv[b * NN + dst];
    const float* xr = xw + ((size_t)b * NN + src) * DD;
    float* orow = out + ((size_t)b * dstmax + dst) * DD;
#pragma unroll
    for (int j = 0; j < 8; j++) {
        int o = lane + j * 32;
        atomicAdd(&orow[o], norm * xr[o]);
    }
}

__global__ void k_post(float* __restrict__ buf, const float* __restrict__ bias,
                       int rows, int dorelu) {
    size_t idx = (size_t)blockIdx.x * 256 + threadIdx.x;
    if (idx >= (size_t)BB * rows * DD) return;
    int o = (int)(idx & (DD - 1));
    float v = buf[idx] + bias[o];
    if (dorelu) v = fmaxf(v, 0.f);
    buf[idx] = to_tf32(v);
}

// ---------------- final MLP --------------------------------------------------
__global__ void k_prepf1(const float* __restrict__ w, float* __restrict__ wT) {
    int idx = blockIdx.x * 256 + threadIdx.x;
    if (idx >= FEAT * FFNH) return;
    int h = idx & (FFNH - 1), k = idx >> 7;
    wT[idx] = w[h * FEAT + k];
}

__global__ void k_final(const float* __restrict__ gout, const float* __restrict__ V,
                        const float* __restrict__ f1T, const float* __restrict__ f1b,
                        const float* __restrict__ f2w, const float* __restrict__ f2b,
                        float* __restrict__ y) {
    __shared__ float s_feat[FEAT];
    __shared__ float s_red[FFNH];
    int c = blockIdx.x, b = blockIdx.y, h = threadIdx.x;   // 128 threads
    for (int idx = h; idx < FEAT; idx += FFNH) {
        float v;
        if (idx < DD) {
            v = gout[((size_t)b * CC + c) * DD + idx];
        } else {
            int br = (idx - DD) / FF;
            int f  = (idx - DD) % FF;
            v = V[(((size_t)br * BB + b) * CC + c) * FF + f];
        }
        s_feat[idx] = v;
    }
    __syncthreads();
    float acc = f1b[h];
    for (int k = 0; k < FEAT; k++) acc += f1T[k * FFNH + h] * s_feat[k];
    float hid = fmaxf(acc, 0.f);
    s_red[h] = f2w[c * FFNH + h] * hid;
    __syncthreads();
    for (int s = 64; s > 0; s >>= 1) {
        if (h < s) s_red[h] += s_red[h + s];
        __syncthreads();
    }
    if (h == 0) y[b * CC + c] = s_red[0] + f2b[c];
}

// ---------------- branch driver ---------------------------------------------
// Launch order inside: wA, wB0, conv1, wB1, conv2, conv3, awp, Z, aup, logits,
// soft, v, vred — so for the FIRST branch, our global launch #4 = conv1 (the
// kernel the -s 5 -c 1 ncu capture lands on).
template<int K>
static void run_branch(const float* cw, const float* cb, const float* rw,
                       const float* bn_g, const float* bn_b,
                       const float* aw, const float* au,
                       float* buf, int br) {
    float* h    = buf + OFF_H;
    float* t0   = buf + OFF_T0;
    float* t1   = buf + OFF_T1;
    float* Z    = buf + OFF_Z;
    float* lg   = buf + OFF_LOG;
    float* rmax = buf + OFF_RMAX;
    float* rsin = buf + OFF_RSINV;
    float* vp   = buf + OFF_VPART;
    float* V    = buf + OFF_V + (size_t)br * BB * CC * FF;
    float* wA   = buf + OFF_WA + (size_t)br * 9 * DD * FP;
    float* wB0  = buf + OFF_WB + (size_t)(br * 2 + 0) * 9 * FP * FP;
    float* wB1  = buf + OFF_WB + (size_t)(br * 2 + 1) * 9 * FP * FP;
    float* awp  = buf + OFF_AWP + (size_t)br * FP * AA;
    float* aup  = buf + OFF_AUP + (size_t)br * AA * 64;

    cudaFuncSetAttribute(k_conv_mma<K, DD>, cudaFuncAttributeMaxDynamicSharedMemorySize,
                         conv_smem_bytes<K, DD>());
    cudaFuncSetAttribute(k_conv_mma<K, FP>, cudaFuncAttributeMaxDynamicSharedMemorySize,
                         conv_smem_bytes<K, FP>());

    dim3 cgrid(LL / 128, BB);
    k_prepw<<<(K * DD * FP + 255) / 256, 256>>>(cw, wA, K, DD, DD);
    k_prepw<<<(K * FP * FP + 255) / 256, 256>>>(rw, wB0, K, FF, FP);
    k_conv_mma<K, DD><<<cgrid, 256, conv_smem_bytes<K, DD>()>>>(
        h, wA, cb, bn_g, bn_b, nullptr, t0, 0);
    k_prepw<<<(K * FP * FP + 255) / 256, 256>>>(rw + (size_t)FF * FF * K, wB1, K, FF, FP);
    k_conv_mma<K, FP><<<cgrid, 256, conv_smem_bytes<K, FP>()>>>(
        t0, wB0, nullptr, bn_g + FF, bn_b + FF, t0, t1, 1);
    k_conv_mma<K, FP><<<cgrid, 256, conv_smem_bytes<K, FP>()>>>(
        t1, wB1, nullptr, bn_g + 2 * FF, bn_b + 2 * FF, t1, t0, 1);

    // Z[b][l][a] = tanh(t0 . aw^T)
    k_prep_bt<<<(FP * AA + 255) / 256, 256>>>(aw, awp, AA, FF, AA, FP);
    k_mma_nt<FP, 2, true, false><<<dim3(LL / 128, AA / 128, BB), 256>>>(
        t0, awp, Z, AA, (size_t)LL * FP, (size_t)LL * AA, AA, 0);
    // logits[b][c][l] = Z . au^T (transposed store)
    k_prep_bt<<<(AA * 64 + 255) / 256, 256>>>(au, aup, CC, AA, 64, AA);
    k_mma_nt<AA, 1, false, true><<<dim3(LL / 128, 1, BB), 128>>>(
        Z, aup, lg, 64, (size_t)LL * AA, (size_t)CC * LL, 0, CC);

    k_soft<<<dim3(CC, BB), 256>>>(lg, rmax, rsin);
    k_v<<<dim3(2, 16, BB), 128>>>(t0, lg, rmax, rsin, vp);
    k_vred<<<(BB * CC * FF + 255) / 256, 256>>>(vp, V);
}

extern "C" void kernel_launch(void* const* d_in, const int* in_sizes, int n_in,
                              void* d_out, int out_size) {
    const int*   x        = (const int*)d_in[0];
    const int*   nodes    = (const int*)d_in[2];
    const int*   edges    = (const int*)d_in[3];
    const float* word_emb = (const float*)d_in[4];
    const float* ent_emb  = (const float*)d_in[5];
    const float* convw3   = (const float*)d_in[6];
    const float* convb3   = (const float*)d_in[7];
    const float* resw3    = (const float*)d_in[8];
    const float* convw5   = (const float*)d_in[9];
    const float* convb5   = (const float*)d_in[10];
    const float* resw5    = (const float*)d_in[11];
    const float* convw9   = (const float*)d_in[12];
    const float* convb9   = (const float*)d_in[13];
    const float* resw9    = (const float*)d_in[14];
    const float* bn_gamma = (const float*)d_in[15];
    const float* bn_beta  = (const float*)d_in[16];
    const float* attn_w   = (const float*)d_in[17];
    const float* attn_u   = (const float*)d_in[18];
    const float* gc1_w    = (const float*)d_in[19];
    const float* gc1_b    = (const float*)d_in[20];
    const float* gc2_w    = (const float*)d_in[21];
    const float* gc2_b    = (const float*)d_in[22];
    const float* fin1_w   = (const float*)d_in[23];
    const float* fin1_b   = (const float*)d_in[24];
    const float* fin2_w   = (const float*)d_in[25];
    const float* fin2_b   = (const float*)d_in[26];
    float* out = (float*)d_out;

    float* buf; int* deg;
    cudaGetSymbolAddress((void**)&buf, g_buf);
    cudaGetSymbolAddress((void**)&deg, g_deg);

    // our launch 1: embedding; then branch K=9 (our launches 2,3 = preps, 4 = conv<9,256>)
    k_embed<<<(int)(((size_t)BB * LL * DD + 255) / 256), 256>>>(x, word_emb, buf + OFF_H);

    run_branch<9>(convw9, convb9, resw9, bn_gamma + 2 * 3 * FF, bn_beta + 2 * 3 * FF,
                  attn_w + 2 * AA * FF, attn_u + 2 * CC * AA, buf, 2);
    run_branch<3>(convw3, convb3, resw3, bn_gamma + 0 * 3 * FF, bn_beta + 0 * 3 * FF,
                  attn_w + 0 * AA * FF, attn_u + 0 * CC * AA, buf, 0);
    run_branch<5>(convw5, convb5, resw5, bn_gamma + 1 * 3 * FF, bn_beta + 1 * 3 * FF,
                  attn_w + 1 * AA * FF, attn_u + 1 * CC * AA, buf, 1);

    // GCN
    float* xn   = buf + OFF_XN;
    float* xw   = buf + OFF_XW;
    float* g1   = buf + OFF_G1;
    float* gout = buf + OFF_GOUT;
    float* dinv = buf + OFF_DINV;
    float* gwt1 = buf + OFF_GWT;
    float* gwt2 = buf + OFF_GWT + (size_t)DD * DD;
    k_nodes<<<(int)(((size_t)BB * NN * DD + 255) / 256), 256>>>(nodes, ent_emb, xn);
    k_deginit<<<(BB * NN + 255) / 256, 256>>>(deg);
    k_degadd<<<(BB * EE + 255) / 256, 256>>>(edges, deg);
    k_dinv<<<(BB * NN + 255) / 256, 256>>>(deg, dinv);

    k_prep_bt<<<(DD * DD + 255) / 256, 256>>>(gc1_w, gwt1, DD, DD, DD, DD);
    k_mma_nt<DD, 2, false, false><<<dim3(NN / 128, DD / 128, BB), 256>>>(
        xn, gwt1, xw, DD, (size_t)NN * DD, (size_t)NN * DD, DD, 0);
    k_self<<<(int)(((size_t)BB * NN * DD + 255) / 256), 256>>>(xw, dinv, g1, NN);
    k_edge<<<dim3(EE / 8, BB), 256>>>(edges, dinv, xw, g1, NN);
    k_post<<<(int)(((size_t)BB * NN * DD + 255) / 256), 256>>>(g1, gc1_b, NN, 1);

    k_prep_bt<<<(DD * DD + 255) / 256, 256>>>(gc2_w, gwt2, DD, DD, DD, DD);
    k_mma_nt<DD, 2, false, false><<<dim3(NN / 128, DD / 128, BB), 256>>>(
        g1, gwt2, xw, DD, (size_t)NN * DD, (size_t)NN * DD, DD, 0);
    k_self<<<(int)(((size_t)BB * CC * DD + 255) / 256), 256>>>(xw, dinv, gout, CC);
    k_edge<<<dim3(EE / 8, BB), 256>>>(edges, dinv, xw, gout, CC);
    k_post<<<(int)(((size_t)BB * CC * DD + 255) / 256), 256>>>(gout, gc2_b, CC, 0);

    // final MLP
    k_prepf1<<<(FEAT * FFNH + 255) / 256, 256>>>(fin1_w, buf + OFF_F1T);
    k_final<<<dim3(CC, BB), FFNH>>>(gout, buf + OFF_V, buf + OFF_F1T,
                                    fin1_b, fin2_w, fin2_b, out);
}